// round 6
// baseline (speedup 1.0000x reference)
#include <cuda_runtime.h>
#include <math.h>

#define TT   2
#define NN   10000
#define EE   60000
#define HH   8
#define FIN  2048
#define F1   1024
#define D1   128
#define F2   512
#define D2   64
#define NOUT 8

// ---------------- device scratch (no runtime allocation allowed) ----------------
__device__ float g_K1[TT*NN*F1];
__device__ float g_Q1[TT*NN*F1];
__device__ float g_V1[TT*NN*F1];
__device__ float g_Krel1[4*NN*F1];
__device__ float g_Vrel1[4*NN*F1];
__device__ float g_att1[TT*NN*F1];
__device__ float g_gel[TT*NN*F1];
__device__ float g_h1[TT*NN*F1];
__device__ float g_K2[TT*NN*F2];
__device__ float g_Q2[TT*NN*F2];
__device__ float g_V2[TT*NN*F2];
__device__ float g_Krel2[4*NN*F2];
__device__ float g_Vrel2[4*NN*F2];
__device__ float g_att2[TT*NN*F2];
__device__ float g_h2[TT*NN*F2];
__device__ float g_alpha[4*EE*HH];
__device__ float g_smax[4*NN*HH];
__device__ float g_ssum[4*NN*HH];
__device__ int   g_edges[4*2*EE];

// ---------------- generic tiled fp32 GEMM: C = A@B + bias, batched over z ------
#define BM 64
#define BN 64
#define BK 16
#define TM 4
#define TN 4

__global__ void gemm_kernel(const float* __restrict__ A, const float* __restrict__ B,
                            const float* __restrict__ bias, float* __restrict__ C,
                            int M, int Nc, int K,
                            long sA, long sB, long sC, long sBias)
{
    int bz = blockIdx.z;
    A += (long)bz * sA;
    B += (long)bz * sB;
    C += (long)bz * sC;
    const float* biasp = bias + (long)bz * sBias;

    __shared__ float As[BK][BM + 1];
    __shared__ float Bs[BK][BN];

    int tid = threadIdx.x;          // 256 threads
    int tx = tid & 15, ty = tid >> 4;
    int m0 = blockIdx.y * BM;
    int n0 = blockIdx.x * BN;

    float acc[TM][TN];
#pragma unroll
    for (int i = 0; i < TM; i++)
#pragma unroll
        for (int j = 0; j < TN; j++) acc[i][j] = 0.f;

    for (int k0 = 0; k0 < K; k0 += BK) {
#pragma unroll
        for (int i = 0; i < 4; i++) {
            int e = tid + i * 256;
            int r = e >> 4, c = e & 15;
            int m = m0 + r;
            float v = 0.f;
            if (m < M) v = A[(long)m * K + k0 + c];
            As[c][r] = v;
        }
#pragma unroll
        for (int i = 0; i < 4; i++) {
            int e = tid + i * 256;
            int r = e >> 6, c = e & 63;
            Bs[r][c] = B[(long)(k0 + r) * Nc + n0 + c];
        }
        __syncthreads();
#pragma unroll
        for (int kk = 0; kk < BK; kk++) {
            float a[TM], b[TN];
#pragma unroll
            for (int i = 0; i < TM; i++) a[i] = As[kk][ty * TM + i];
#pragma unroll
            for (int j = 0; j < TN; j++) b[j] = Bs[kk][tx * TN + j];
#pragma unroll
            for (int i = 0; i < TM; i++)
#pragma unroll
                for (int j = 0; j < TN; j++) acc[i][j] += a[i] * b[j];
        }
        __syncthreads();
    }
#pragma unroll
    for (int i = 0; i < TM; i++) {
        int m = m0 + ty * TM + i;
        if (m >= M) continue;
#pragma unroll
        for (int j = 0; j < TN; j++) {
            int n = n0 + tx * TN + j;
            C[(long)m * Nc + n] = acc[i][j] + biasp[n];
        }
    }
}

// ------------- per-(edge-type,head) relation GEMM: out[e,n,h,:] = KQV[st,n,h,:] @ rel[e,h] -------------
__global__ void rel_gemm_kernel(const float* __restrict__ KQV,  // [TT, NN, H*D]
                                const float* __restrict__ rel,  // [4, H, D, D]
                                float* __restrict__ outp,       // [4, NN, H*D]
                                int D)
{
    int z = blockIdx.z;            // 0..31
    int e = z >> 3;
    int h = z & 7;
    int st = e >> 1;
    int HD = HH * D;
    const float* A = KQV + (long)st * NN * HD + h * D;        // lda = HD, K = D
    const float* B = rel + (((long)e * HH + h) * D) * D;      // [D, D]
    float* C = outp + (long)e * NN * HD + h * D;              // ldc = HD

    __shared__ float As[BK][BM + 1];
    __shared__ float Bs[BK][BN];

    int tid = threadIdx.x;
    int tx = tid & 15, ty = tid >> 4;
    int m0 = blockIdx.y * BM;
    int n0 = blockIdx.x * BN;

    float acc[TM][TN];
#pragma unroll
    for (int i = 0; i < TM; i++)
#pragma unroll
        for (int j = 0; j < TN; j++) acc[i][j] = 0.f;

    for (int k0 = 0; k0 < D; k0 += BK) {
#pragma unroll
        for (int i = 0; i < 4; i++) {
            int e2 = tid + i * 256;
            int r = e2 >> 4, c = e2 & 15;
            int m = m0 + r;
            float v = 0.f;
            if (m < NN) v = A[(long)m * HD + k0 + c];
            As[c][r] = v;
        }
#pragma unroll
        for (int i = 0; i < 4; i++) {
            int e2 = tid + i * 256;
            int r = e2 >> 6, c = e2 & 63;
            Bs[r][c] = B[(long)(k0 + r) * D + n0 + c];
        }
        __syncthreads();
#pragma unroll
        for (int kk = 0; kk < BK; kk++) {
            float a[TM], b[TN];
#pragma unroll
            for (int i = 0; i < TM; i++) a[i] = As[kk][ty * TM + i];
#pragma unroll
            for (int j = 0; j < TN; j++) b[j] = Bs[kk][tx * TN + j];
#pragma unroll
            for (int i = 0; i < TM; i++)
#pragma unroll
                for (int j = 0; j < TN; j++) acc[i][j] += a[i] * b[j];
        }
        __syncthreads();
    }
#pragma unroll
    for (int i = 0; i < TM; i++) {
        int m = m0 + ty * TM + i;
        if (m >= NN) continue;
#pragma unroll
        for (int j = 0; j < TN; j++) {
            int n = n0 + tx * TN + j;
            C[(long)m * HD + n] = acc[i][j];
        }
    }
}

// ---------------- attention ----------------
__device__ __forceinline__ void atomicMaxFloat(float* addr, float val)
{
    if (val >= 0.f) atomicMax((int*)addr, __float_as_int(val));
    else            atomicMin((unsigned int*)addr, __float_as_uint(val));
}

__global__ void fill_kernel(float* __restrict__ p, float v, long n)
{
    long i = (long)blockIdx.x * blockDim.x + threadIdx.x;
    long stride = (long)gridDim.x * blockDim.x;
    for (; i < n; i += stride) p[i] = v;
}

// warp per edge: alpha_raw[e,edge,h] = dot(Q[dt,dst,h,:], Krel[e,src,h,:]) * prel[e,h]/sqrt(D)
__global__ void attn_logits_kernel(const float* __restrict__ Q,    // [TT,NN,H*D]
                                   const float* __restrict__ Krel, // [4,NN,H*D]
                                   const int* __restrict__ edges,  // [4,2,EE]
                                   const float* __restrict__ prel, // [4,H]
                                   float* __restrict__ alpha,      // [4,EE,H]
                                   float* __restrict__ smax,       // [4,NN,H]
                                   int D)
{
    int e = blockIdx.y;
    int w = (blockIdx.x * blockDim.x + threadIdx.x) >> 5;
    if (w >= EE) return;
    int lane = threadIdx.x & 31;
    int src = edges[e * 2 * EE + w];
    int dst = edges[e * 2 * EE + EE + w];
    int dt = e & 1;
    int HD = HH * D;
    const float* qrow = Q + ((long)dt * NN + dst) * HD;
    const float* krow = Krel + ((long)e * NN + src) * HD;
    float inv = rsqrtf((float)D);
#pragma unroll
    for (int h = 0; h < HH; h++) {
        float acc = 0.f;
        for (int d = lane; d < D; d += 32) acc += qrow[h * D + d] * krow[h * D + d];
#pragma unroll
        for (int o = 16; o; o >>= 1) acc += __shfl_xor_sync(0xffffffffu, acc, o);
        if (lane == 0) {
            float a = acc * prel[e * HH + h] * inv;
            alpha[((long)e * EE + w) * HH + h] = a;
            atomicMaxFloat(&smax[(e * NN + dst) * HH + h], a);
        }
    }
}

__global__ void attn_expsum_kernel(const int* __restrict__ edges,
                                   float* __restrict__ alpha,
                                   const float* __restrict__ smax,
                                   float* __restrict__ ssum)
{
    long i = (long)blockIdx.x * blockDim.x + threadIdx.x;
    if (i >= 4L * EE * HH) return;
    int h = (int)(i % HH);
    long eh = i / HH;
    int edge = (int)(eh % EE);
    int e = (int)(eh / EE);
    int dst = edges[e * 2 * EE + EE + edge];
    float m = smax[(e * NN + dst) * HH + h];
    float v = __expf(alpha[i] - m);
    alpha[i] = v;
    atomicAdd(&ssum[(e * NN + dst) * HH + h], v);
}

// warp per edge: out[dt,dst,h,:] += (alpha/ssum) * Vrel[e,src,h,:]
__global__ void attn_agg_kernel(const float* __restrict__ Vrel,
                                const int* __restrict__ edges,
                                const float* __restrict__ alpha,
                                const float* __restrict__ ssum,
                                float* __restrict__ outp,   // [TT,NN,H*D]
                                int D)
{
    int e = blockIdx.y;
    int w = (blockIdx.x * blockDim.x + threadIdx.x) >> 5;
    if (w >= EE) return;
    int lane = threadIdx.x & 31;
    int src = edges[e * 2 * EE + w];
    int dst = edges[e * 2 * EE + EE + w];
    int dt = e & 1;
    int HD = HH * D;
    const float* vrow = Vrel + ((long)e * NN + src) * HD;
    float* orow = outp + ((long)dt * NN + dst) * HD;
#pragma unroll
    for (int h = 0; h < HH; h++) {
        float coef = alpha[((long)e * EE + w) * HH + h]
                   / (ssum[(e * NN + dst) * HH + h] + 1e-16f);
        for (int d = lane; d < D; d += 32)
            atomicAdd(&orow[h * D + d], coef * vrow[h * D + d]);
    }
}

// ---------------- elementwise exact GELU ----------------
__global__ void gelu_kernel(const float* __restrict__ in, float* __restrict__ out, long n)
{
    long i = (long)blockIdx.x * blockDim.x + threadIdx.x;
    long stride = (long)gridDim.x * blockDim.x;
    for (; i < n; i += stride) {
        float x = in[i];
        out[i] = 0.5f * x * (1.0f + erff(x * 0.7071067811865476f));
    }
}

// ---------------- final: logits = h @ Wlin + blin; row softmax (warp per row) ----------------
__global__ void final_softmax_kernel(const float* __restrict__ h,    // [TT*NN, F2]
                                     const float* __restrict__ Wlin, // [F2, NOUT]
                                     const float* __restrict__ blin, // [NOUT]
                                     float* __restrict__ out)        // [TT*NN, NOUT]
{
    int row = (blockIdx.x * blockDim.x + threadIdx.x) >> 5;
    if (row >= TT * NN) return;
    int lane = threadIdx.x & 31;
    const float* hr = h + (long)row * F2;
    float acc[NOUT];
#pragma unroll
    for (int o = 0; o < NOUT; o++) acc[o] = 0.f;
    for (int f = lane; f < F2; f += 32) {
        float hv = hr[f];
#pragma unroll
        for (int o = 0; o < NOUT; o++) acc[o] += hv * Wlin[f * NOUT + o];
    }
#pragma unroll
    for (int o = 0; o < NOUT; o++)
#pragma unroll
        for (int s = 16; s; s >>= 1) acc[o] += __shfl_xor_sync(0xffffffffu, acc[o], s);
    if (lane == 0) {
        float vals[NOUT];
        float m = -INFINITY;
#pragma unroll
        for (int o = 0; o < NOUT; o++) { vals[o] = acc[o] + blin[o]; m = fmaxf(m, vals[o]); }
        float s = 0.f;
#pragma unroll
        for (int o = 0; o < NOUT; o++) { vals[o] = __expf(vals[o] - m); s += vals[o]; }
        float invs = 1.0f / s;
#pragma unroll
        for (int o = 0; o < NOUT; o++) out[(long)row * NOUT + o] = vals[o] * invs;
    }
}

// ---------------- host orchestration ----------------
static float* sym(const void* s)
{
    void* p = nullptr;
    cudaGetSymbolAddress(&p, (const void*)s);
    return (float*)p;
}

extern "C" void kernel_launch(void* const* d_in, const int* in_sizes, int n_in,
                              void* d_out, int out_size)
{
    const float* x     = (const float*)d_in[0];
    const int*   ei[4] = { (const int*)d_in[1], (const int*)d_in[2],
                           (const int*)d_in[3], (const int*)d_in[4] };
    const float* Wk1 = (const float*)d_in[5];  const float* bk1 = (const float*)d_in[6];
    const float* Wq1 = (const float*)d_in[7];  const float* bq1 = (const float*)d_in[8];
    const float* Wv1 = (const float*)d_in[9];  const float* bv1 = (const float*)d_in[10];
    const float* Wa1 = (const float*)d_in[11]; const float* ba1 = (const float*)d_in[12];
    const float* arel1 = (const float*)d_in[13];
    const float* mrel1 = (const float*)d_in[14];
    const float* prel1 = (const float*)d_in[15];
    const float* Wk2 = (const float*)d_in[16]; const float* bk2 = (const float*)d_in[17];
    const float* Wq2 = (const float*)d_in[18]; const float* bq2 = (const float*)d_in[19];
    const float* Wv2 = (const float*)d_in[20]; const float* bv2 = (const float*)d_in[21];
    const float* Wa2 = (const float*)d_in[22]; const float* ba2 = (const float*)d_in[23];
    const float* arel2 = (const float*)d_in[24];
    const float* mrel2 = (const float*)d_in[25];
    const float* prel2 = (const float*)d_in[26];
    const float* Wlin  = (const float*)d_in[27];
    const float* blin  = (const float*)d_in[28];

    float* K1 = sym(g_K1);   float* Q1 = sym(g_Q1);   float* V1 = sym(g_V1);
    float* Kr1 = sym(g_Krel1); float* Vr1 = sym(g_Vrel1);
    float* att1 = sym(g_att1); float* gel = sym(g_gel); float* h1 = sym(g_h1);
    float* K2 = sym(g_K2);   float* Q2 = sym(g_Q2);   float* V2 = sym(g_V2);
    float* Kr2 = sym(g_Krel2); float* Vr2 = sym(g_Vrel2);
    float* att2 = sym(g_att2); float* h2 = sym(g_h2);
    float* alpha = sym(g_alpha); float* smax = sym(g_smax); float* ssum = sym(g_ssum);
    int* edges = (int*)sym(g_edges);

    for (int e = 0; e < 4; e++)
        cudaMemcpyAsync(edges + e * 2 * EE, ei[e], (size_t)2 * EE * sizeof(int),
                        cudaMemcpyDeviceToDevice, 0);

    dim3 blk(256);
    int mtiles = (NN + BM - 1) / BM;

    // ===================== Layer 1 =====================
    {
        dim3 g(F1 / BN, mtiles, TT);
        gemm_kernel<<<g, blk>>>(x, Wk1, bk1, K1, NN, F1, FIN,
                                (long)NN * FIN, (long)FIN * F1, (long)NN * F1, F1);
        gemm_kernel<<<g, blk>>>(x, Wq1, bq1, Q1, NN, F1, FIN,
                                (long)NN * FIN, (long)FIN * F1, (long)NN * F1, F1);
        gemm_kernel<<<g, blk>>>(x, Wv1, bv1, V1, NN, F1, FIN,
                                (long)NN * FIN, (long)FIN * F1, (long)NN * F1, F1);
    }
    {
        dim3 g(D1 / BN, mtiles, 32);
        rel_gemm_kernel<<<g, blk>>>(K1, arel1, Kr1, D1);
        rel_gemm_kernel<<<g, blk>>>(V1, mrel1, Vr1, D1);
    }
    fill_kernel<<<2048, 256>>>(smax, -INFINITY, 4L * NN * HH);
    fill_kernel<<<2048, 256>>>(ssum, 0.f, 4L * NN * HH);
    fill_kernel<<<4096, 256>>>(att1, 0.f, (long)TT * NN * F1);

    attn_logits_kernel<<<dim3(EE / 8, 4), blk>>>(Q1, Kr1, edges, prel1, alpha, smax, D1);
    attn_expsum_kernel<<<(4 * EE * HH + 255) / 256, blk>>>(edges, alpha, smax, ssum);
    attn_agg_kernel<<<dim3(EE / 8, 4), blk>>>(Vr1, edges, alpha, ssum, att1, D1);

    gelu_kernel<<<4096, 256>>>(att1, gel, (long)TT * NN * F1);
    {
        dim3 g(F1 / BN, mtiles, TT);
        gemm_kernel<<<g, blk>>>(gel, Wa1, ba1, h1, NN, F1, F1,
                                (long)NN * F1, (long)F1 * F1, (long)NN * F1, F1);
    }

    // ===================== Layer 2 =====================
    {
        dim3 g(F2 / BN, mtiles, TT);
        gemm_kernel<<<g, blk>>>(h1, Wk2, bk2, K2, NN, F2, F1,
                                (long)NN * F1, (long)F1 * F2, (long)NN * F2, F2);
        gemm_kernel<<<g, blk>>>(h1, Wq2, bq2, Q2, NN, F2, F1,
                                (long)NN * F1, (long)F1 * F2, (long)NN * F2, F2);
        gemm_kernel<<<g, blk>>>(h1, Wv2, bv2, V2, NN, F2, F1,
                                (long)NN * F1, (long)F1 * F2, (long)NN * F2, F2);
    }
    {
        dim3 g(D2 / BN, mtiles, 32);
        rel_gemm_kernel<<<g, blk>>>(K2, arel2, Kr2, D2);
        rel_gemm_kernel<<<g, blk>>>(V2, mrel2, Vr2, D2);
    }
    fill_kernel<<<2048, 256>>>(smax, -INFINITY, 4L * NN * HH);
    fill_kernel<<<2048, 256>>>(ssum, 0.f, 4L * NN * HH);
    fill_kernel<<<4096, 256>>>(att2, 0.f, (long)TT * NN * F2);

    attn_logits_kernel<<<dim3(EE / 8, 4), blk>>>(Q2, Kr2, edges, prel2, alpha, smax, D2);
    attn_expsum_kernel<<<(4 * EE * HH + 255) / 256, blk>>>(edges, alpha, smax, ssum);
    attn_agg_kernel<<<dim3(EE / 8, 4), blk>>>(Vr2, edges, alpha, ssum, att2, D2);

    gelu_kernel<<<4096, 256>>>(att2, gel, (long)TT * NN * F2);
    {
        dim3 g(F2 / BN, mtiles, TT);
        gemm_kernel<<<g, blk>>>(gel, Wa2, ba2, h2, NN, F2, F2,
                                (long)NN * F2, (long)F2 * F2, (long)NN * F2, F2);
    }

    // ===================== Final linear + softmax =====================
    final_softmax_kernel<<<(TT * NN * 32 + 255) / 256, blk>>>(h2, Wlin, blin, (float*)d_out);
}

// round 11
// speedup vs baseline: 3.2109x; 3.2109x over previous
#include <cuda_runtime.h>
#include <math.h>

#define TT   2
#define NN   10000
#define EE   60000
#define HH   8
#define FIN  2048
#define F1   1024
#define D1   128
#define F2   512
#define D2   64
#define NOUT 8

// ---------------- device scratch (no runtime allocation allowed) ----------------
__device__ float g_K1[TT*NN*F1];
__device__ float g_Q1[TT*NN*F1];
__device__ float g_V1[TT*NN*F1];
__device__ float g_Krel1[4*NN*F1];
__device__ float g_Vrel1[4*NN*F1];
__device__ float g_att1[TT*NN*F1];
__device__ float g_gel[TT*NN*F1];
__device__ float g_h1[TT*NN*F1];
__device__ float g_K2[TT*NN*F2];
__device__ float g_Q2[TT*NN*F2];
__device__ float g_V2[TT*NN*F2];
__device__ float g_Krel2[4*NN*F2];
__device__ float g_Vrel2[4*NN*F2];
__device__ float g_att2[TT*NN*F2];
__device__ float g_h2[TT*NN*F2];
__device__ float g_alpha[4*EE*HH];
__device__ float g_smax[4*NN*HH];
__device__ float g_ssum[4*NN*HH];
__device__ int   g_edges[4*2*EE];

// =================== TF32 tensor-core GEMM ===================
// Block tile 128x128x32, 256 threads = 8 warps arranged 2(M) x 4(N),
// warp tile 64x32 built from m16n8k8 tf32 MMAs (mtiles=4, ntiles=4).
// cp.async double-buffered smem. Padding makes fragment LDS conflict-free.
#define GBM 128
#define GBN 128
#define GBK 32
#define APAD 4      // As row stride = 36 -> fragment banks 4*grp+tg (distinct)
#define BPAD 4      // Bs row stride = 132 -> fragment banks 4*tg+grp (distinct)
#define AS_STRIDE (GBK + APAD)
#define BS_STRIDE (GBN + BPAD)
#define AS_ELEMS (GBM * AS_STRIDE)          // per buffer
#define BS_ELEMS (GBK * BS_STRIDE)
#define GEMM_SMEM_BYTES ((2 * AS_ELEMS + 2 * BS_ELEMS) * 4)

__device__ __forceinline__ void cp16(unsigned* dst_smem, const float* src, bool pred)
{
    unsigned d = (unsigned)__cvta_generic_to_shared(dst_smem);
    int sz = pred ? 16 : 0;   // src-size 0 => zero-fill, no global access
    asm volatile("cp.async.cg.shared.global [%0], [%1], 16, %2;\n"
                 :: "r"(d), "l"(src), "r"(sz));
}

__device__ __forceinline__ void mma_tf32(float c[4],
                                         unsigned a0, unsigned a1, unsigned a2, unsigned a3,
                                         unsigned b0, unsigned b1)
{
    asm volatile(
        "mma.sync.aligned.m16n8k8.row.col.f32.tf32.tf32.f32 "
        "{%0,%1,%2,%3}, {%4,%5,%6,%7}, {%8,%9}, {%0,%1,%2,%3};\n"
        : "+f"(c[0]), "+f"(c[1]), "+f"(c[2]), "+f"(c[3])
        : "r"(a0), "r"(a1), "r"(a2), "r"(a3), "r"(b0), "r"(b1));
}

// Core: C[M,N] = A[M,K] @ B[K,N] (+bias). lda/ldb/ldc arbitrary. K % 32 == 0.
__device__ __forceinline__ void gemm_tf32_core(
    unsigned* smem,
    const float* __restrict__ A, long lda,
    const float* __restrict__ B, long ldb,
    const float* __restrict__ bias,
    float* __restrict__ C, long ldc,
    int M, int N, int K)
{
    unsigned* smA = smem;                       // 2 buffers of As
    unsigned* smB = smem + 2 * AS_ELEMS;        // 2 buffers of Bs

    const int tid  = threadIdx.x;
    const int lane = tid & 31;
    const int wid  = tid >> 5;
    const int wm   = wid & 1;        // 0..1  -> 64-row slab
    const int wn   = wid >> 1;       // 0..3  -> 32-col slab
    const int grp  = lane >> 2;      // 0..7
    const int tg   = lane & 3;       // 0..3

    const int m0 = blockIdx.y * GBM;
    const int n0 = blockIdx.x * GBN;

    float acc[4][4][4];
#pragma unroll
    for (int mt = 0; mt < 4; mt++)
#pragma unroll
        for (int nt = 0; nt < 4; nt++)
#pragma unroll
            for (int i = 0; i < 4; i++) acc[mt][nt][i] = 0.f;

    const int niter = K / GBK;

    // ---- async tile loader ----
    auto issue = [&](int k0, int buf) {
        unsigned* Asb = smA + buf * AS_ELEMS;
        unsigned* Bsb = smB + buf * BS_ELEMS;
#pragma unroll
        for (int j = 0; j < 4; j++) {                 // A: 128x32 = 1024 float4
            int i = tid + j * 256;
            int r = i >> 3, kc = (i & 7) * 4;
            int m = m0 + r;
            cp16(Asb + r * AS_STRIDE + kc, A + (long)m * lda + k0 + kc, m < M);
        }
#pragma unroll
        for (int j = 0; j < 4; j++) {                 // B: 32x128 = 1024 float4
            int i = tid + j * 256;
            int r = i >> 5, nc = (i & 31) * 4;        // r: 0..31, nc: 0..124
            int n = n0 + nc;
            cp16(Bsb + r * BS_STRIDE + nc, B + (long)(k0 + r) * ldb + n, n < N);
        }
        asm volatile("cp.async.commit_group;\n");
    };

    issue(0, 0);

    for (int it = 0; it < niter; ++it) {
        if (it + 1 < niter) {
            issue((it + 1) * GBK, (it + 1) & 1);
            asm volatile("cp.async.wait_group 1;\n");
        } else {
            asm volatile("cp.async.wait_group 0;\n");
        }
        __syncthreads();

        unsigned* Asb = smA + (it & 1) * AS_ELEMS;
        unsigned* Bsb = smB + (it & 1) * BS_ELEMS;

#pragma unroll
        for (int ks = 0; ks < GBK / 8; ks++) {
            const int kk = ks * 8;
            unsigned a[4][4], b[4][2];
#pragma unroll
            for (int mt = 0; mt < 4; mt++) {
                int r = wm * 64 + mt * 16 + grp;
                a[mt][0] = Asb[r * AS_STRIDE + kk + tg];
                a[mt][1] = Asb[(r + 8) * AS_STRIDE + kk + tg];
                a[mt][2] = Asb[r * AS_STRIDE + kk + tg + 4];
                a[mt][3] = Asb[(r + 8) * AS_STRIDE + kk + tg + 4];
            }
#pragma unroll
            for (int nt = 0; nt < 4; nt++) {
                int c = wn * 32 + nt * 8 + grp;
                b[nt][0] = Bsb[(kk + tg) * BS_STRIDE + c];
                b[nt][1] = Bsb[(kk + tg + 4) * BS_STRIDE + c];
            }
#pragma unroll
            for (int mt = 0; mt < 4; mt++)
#pragma unroll
                for (int nt = 0; nt < 4; nt++)
                    mma_tf32(acc[mt][nt], a[mt][0], a[mt][1], a[mt][2], a[mt][3],
                             b[nt][0], b[nt][1]);
        }
        __syncthreads();
    }

    // ---- epilogue: bias + store (float2) ----
#pragma unroll
    for (int mt = 0; mt < 4; mt++) {
        int r0 = m0 + wm * 64 + mt * 16 + grp;
#pragma unroll
        for (int nt = 0; nt < 4; nt++) {
            int col = n0 + wn * 32 + nt * 8 + tg * 2;
            if (col >= N) continue;
            float bx = 0.f, by = 0.f;
            if (bias) { bx = bias[col]; by = bias[col + 1]; }
            if (r0 < M) {
                float2 v = make_float2(acc[mt][nt][0] + bx, acc[mt][nt][1] + by);
                *(float2*)(C + (long)r0 * ldc + col) = v;
            }
            if (r0 + 8 < M) {
                float2 v = make_float2(acc[mt][nt][2] + bx, acc[mt][nt][3] + by);
                *(float2*)(C + (long)(r0 + 8) * ldc + col) = v;
            }
        }
    }
}

// Batched dense GEMM over z: C[z] = A[z] @ B[z] + bias[z]
__global__ __launch_bounds__(256, 2)
void gemm_tf32_kernel(const float* __restrict__ A, const float* __restrict__ B,
                      const float* __restrict__ bias, float* __restrict__ C,
                      int M, int N, int K,
                      long sA, long sB, long sC, long sBias)
{
    extern __shared__ unsigned smem_u[];
    int bz = blockIdx.z;
    gemm_tf32_core(smem_u,
                   A + (long)bz * sA, K,
                   B + (long)bz * sB, N,
                   bias + (long)bz * sBias,
                   C + (long)bz * sC, N,
                   M, N, K);
}

// Per-(edge-type, head) relation GEMM: out[e,n,h,:] = KQV[st,n,h,:] @ rel[e,h]
__global__ __launch_bounds__(256, 2)
void rel_gemm_tf32_kernel(const float* __restrict__ KQV,  // [TT,NN,H*D]
                          const float* __restrict__ rel,  // [4,H,D,D]
                          float* __restrict__ outp,       // [4,NN,H*D]
                          int D)
{
    extern __shared__ unsigned smem_u[];
    int z = blockIdx.z;            // 0..31
    int e = z >> 3;
    int h = z & 7;
    int st = e >> 1;
    int HD = HH * D;
    gemm_tf32_core(smem_u,
                   KQV + (long)st * NN * HD + h * D, HD,
                   rel + ((long)e * HH + h) * (long)D * D, D,
                   nullptr,
                   outp + (long)e * NN * HD + h * D, HD,
                   NN, D, D);
}

// ---------------- attention ----------------
__device__ __forceinline__ void atomicMaxFloat(float* addr, float val)
{
    if (val >= 0.f) atomicMax((int*)addr, __float_as_int(val));
    else            atomicMin((unsigned int*)addr, __float_as_uint(val));
}

__global__ void fill_kernel(float* __restrict__ p, float v, long n)
{
    long i = (long)blockIdx.x * blockDim.x + threadIdx.x;
    long stride = (long)gridDim.x * blockDim.x;
    for (; i < n; i += stride) p[i] = v;
}

__global__ void attn_logits_kernel(const float* __restrict__ Q,    // [TT,NN,H*D]
                                   const float* __restrict__ Krel, // [4,NN,H*D]
                                   const int* __restrict__ edges,  // [4,2,EE]
                                   const float* __restrict__ prel, // [4,H]
                                   float* __restrict__ alpha,      // [4,EE,H]
                                   float* __restrict__ smax,       // [4,NN,H]
                                   int D)
{
    int e = blockIdx.y;
    int w = (blockIdx.x * blockDim.x + threadIdx.x) >> 5;
    if (w >= EE) return;
    int lane = threadIdx.x & 31;
    int src = edges[e * 2 * EE + w];
    int dst = edges[e * 2 * EE + EE + w];
    int dt = e & 1;
    int HD = HH * D;
    const float* qrow = Q + ((long)dt * NN + dst) * HD;
    const float* krow = Krel + ((long)e * NN + src) * HD;
    float inv = rsqrtf((float)D);
#pragma unroll
    for (int h = 0; h < HH; h++) {
        float acc = 0.f;
        for (int d = lane; d < D; d += 32) acc += qrow[h * D + d] * krow[h * D + d];
#pragma unroll
        for (int o = 16; o; o >>= 1) acc += __shfl_xor_sync(0xffffffffu, acc, o);
        if (lane == 0) {
            float a = acc * prel[e * HH + h] * inv;
            alpha[((long)e * EE + w) * HH + h] = a;
            atomicMaxFloat(&smax[(e * NN + dst) * HH + h], a);
        }
    }
}

__global__ void attn_expsum_kernel(const int* __restrict__ edges,
                                   float* __restrict__ alpha,
                                   const float* __restrict__ smax,
                                   float* __restrict__ ssum)
{
    long i = (long)blockIdx.x * blockDim.x + threadIdx.x;
    if (i >= 4L * EE * HH) return;
    int h = (int)(i % HH);
    long eh = i / HH;
    int edge = (int)(eh % EE);
    int e = (int)(eh / EE);
    int dst = edges[e * 2 * EE + EE + edge];
    float m = smax[(e * NN + dst) * HH + h];
    float v = __expf(alpha[i] - m);
    alpha[i] = v;
    atomicAdd(&ssum[(e * NN + dst) * HH + h], v);
}

__global__ void attn_agg_kernel(const float* __restrict__ Vrel,
                                const int* __restrict__ edges,
                                const float* __restrict__ alpha,
                                const float* __restrict__ ssum,
                                float* __restrict__ outp,   // [TT,NN,H*D]
                                int D)
{
    int e = blockIdx.y;
    int w = (blockIdx.x * blockDim.x + threadIdx.x) >> 5;
    if (w >= EE) return;
    int lane = threadIdx.x & 31;
    int src = edges[e * 2 * EE + w];
    int dst = edges[e * 2 * EE + EE + w];
    int dt = e & 1;
    int HD = HH * D;
    const float* vrow = Vrel + ((long)e * NN + src) * HD;
    float* orow = outp + ((long)dt * NN + dst) * HD;
#pragma unroll
    for (int h = 0; h < HH; h++) {
        float coef = alpha[((long)e * EE + w) * HH + h]
                   / (ssum[(e * NN + dst) * HH + h] + 1e-16f);
        for (int d = lane; d < D; d += 32)
            atomicAdd(&orow[h * D + d], coef * vrow[h * D + d]);
    }
}

// ---------------- elementwise exact GELU ----------------
__global__ void gelu_kernel(const float* __restrict__ in, float* __restrict__ out, long n)
{
    long i = (long)blockIdx.x * blockDim.x + threadIdx.x;
    long stride = (long)gridDim.x * blockDim.x;
    for (; i < n; i += stride) {
        float x = in[i];
        out[i] = 0.5f * x * (1.0f + erff(x * 0.7071067811865476f));
    }
}

// ---------------- final: logits = h @ Wlin + blin; row softmax ----------------
__global__ void final_softmax_kernel(const float* __restrict__ h,    // [TT*NN, F2]
                                     const float* __restrict__ Wlin, // [F2, NOUT]
                                     const float* __restrict__ blin, // [NOUT]
                                     float* __restrict__ out)        // [TT*NN, NOUT]
{
    int row = (blockIdx.x * blockDim.x + threadIdx.x) >> 5;
    if (row >= TT * NN) return;
    int lane = threadIdx.x & 31;
    const float* hr = h + (long)row * F2;
    float acc[NOUT];
#pragma unroll
    for (int o = 0; o < NOUT; o++) acc[o] = 0.f;
    for (int f = lane; f < F2; f += 32) {
        float hv = hr[f];
#pragma unroll
        for (int o = 0; o < NOUT; o++) acc[o] += hv * Wlin[f * NOUT + o];
    }
#pragma unroll
    for (int o = 0; o < NOUT; o++)
#pragma unroll
        for (int s = 16; s; s >>= 1) acc[o] += __shfl_xor_sync(0xffffffffu, acc[o], s);
    if (lane == 0) {
        float vals[NOUT];
        float m = -INFINITY;
#pragma unroll
        for (int o = 0; o < NOUT; o++) { vals[o] = acc[o] + blin[o]; m = fmaxf(m, vals[o]); }
        float s = 0.f;
#pragma unroll
        for (int o = 0; o < NOUT; o++) { vals[o] = __expf(vals[o] - m); s += vals[o]; }
        float invs = 1.0f / s;
#pragma unroll
        for (int o = 0; o < NOUT; o++) out[(long)row * NOUT + o] = vals[o] * invs;
    }
}

// ---------------- host orchestration ----------------
static float* sym(const void* s)
{
    void* p = nullptr;
    cudaGetSymbolAddress(&p, (const void*)s);
    return (float*)p;
}

extern "C" void kernel_launch(void* const* d_in, const int* in_sizes, int n_in,
                              void* d_out, int out_size)
{
    const float* x     = (const float*)d_in[0];
    const int*   ei[4] = { (const int*)d_in[1], (const int*)d_in[2],
                           (const int*)d_in[3], (const int*)d_in[4] };
    const float* Wk1 = (const float*)d_in[5];  const float* bk1 = (const float*)d_in[6];
    const float* Wq1 = (const float*)d_in[7];  const float* bq1 = (const float*)d_in[8];
    const float* Wv1 = (const float*)d_in[9];  const float* bv1 = (const float*)d_in[10];
    const float* Wa1 = (const float*)d_in[11]; const float* ba1 = (const float*)d_in[12];
    const float* arel1 = (const float*)d_in[13];
    const float* mrel1 = (const float*)d_in[14];
    const float* prel1 = (const float*)d_in[15];
    const float* Wk2 = (const float*)d_in[16]; const float* bk2 = (const float*)d_in[17];
    const float* Wq2 = (const float*)d_in[18]; const float* bq2 = (const float*)d_in[19];
    const float* Wv2 = (const float*)d_in[20]; const float* bv2 = (const float*)d_in[21];
    const float* Wa2 = (const float*)d_in[22]; const float* ba2 = (const float*)d_in[23];
    const float* arel2 = (const float*)d_in[24];
    const float* mrel2 = (const float*)d_in[25];
    const float* prel2 = (const float*)d_in[26];
    const float* Wlin  = (const float*)d_in[27];
    const float* blin  = (const float*)d_in[28];

    float* K1 = sym(g_K1);   float* Q1 = sym(g_Q1);   float* V1 = sym(g_V1);
    float* Kr1 = sym(g_Krel1); float* Vr1 = sym(g_Vrel1);
    float* att1 = sym(g_att1); float* gel = sym(g_gel); float* h1 = sym(g_h1);
    float* K2 = sym(g_K2);   float* Q2 = sym(g_Q2);   float* V2 = sym(g_V2);
    float* Kr2 = sym(g_Krel2); float* Vr2 = sym(g_Vrel2);
    float* att2 = sym(g_att2); float* h2 = sym(g_h2);
    float* alpha = sym(g_alpha); float* smax = sym(g_smax); float* ssum = sym(g_ssum);
    int* edges = (int*)sym(g_edges);

    cudaFuncSetAttribute(gemm_tf32_kernel,
                         cudaFuncAttributeMaxDynamicSharedMemorySize, GEMM_SMEM_BYTES);
    cudaFuncSetAttribute(rel_gemm_tf32_kernel,
                         cudaFuncAttributeMaxDynamicSharedMemorySize, GEMM_SMEM_BYTES);

    for (int e = 0; e < 4; e++)
        cudaMemcpyAsync(edges + e * 2 * EE, ei[e], (size_t)2 * EE * sizeof(int),
                        cudaMemcpyDeviceToDevice, 0);

    dim3 blk(256);
    int mtiles = (NN + GBM - 1) / GBM;   // 79

    // ===================== Layer 1 =====================
    {
        dim3 g(F1 / GBN, mtiles, TT);
        gemm_tf32_kernel<<<g, blk, GEMM_SMEM_BYTES>>>(x, Wk1, bk1, K1, NN, F1, FIN,
                                (long)NN * FIN, (long)FIN * F1, (long)NN * F1, F1);
        gemm_tf32_kernel<<<g, blk, GEMM_SMEM_BYTES>>>(x, Wq1, bq1, Q1, NN, F1, FIN,
                                (long)NN * FIN, (long)FIN * F1, (long)NN * F1, F1);
        gemm_tf32_kernel<<<g, blk, GEMM_SMEM_BYTES>>>(x, Wv1, bv1, V1, NN, F1, FIN,
                                (long)NN * FIN, (long)FIN * F1, (long)NN * F1, F1);
    }
    {
        dim3 g((D1 + GBN - 1) / GBN, mtiles, 32);
        rel_gemm_tf32_kernel<<<g, blk, GEMM_SMEM_BYTES>>>(K1, arel1, Kr1, D1);
        rel_gemm_tf32_kernel<<<g, blk, GEMM_SMEM_BYTES>>>(V1, mrel1, Vr1, D1);
    }
    fill_kernel<<<2048, 256>>>(smax, -INFINITY, 4L * NN * HH);
    fill_kernel<<<2048, 256>>>(ssum, 0.f, 4L * NN * HH);
    fill_kernel<<<4096, 256>>>(att1, 0.f, (long)TT * NN * F1);

    attn_logits_kernel<<<dim3(EE / 8, 4), blk>>>(Q1, Kr1, edges, prel1, alpha, smax, D1);
    attn_expsum_kernel<<<(4 * EE * HH + 255) / 256, blk>>>(edges, alpha, smax, ssum);
    attn_agg_kernel<<<dim3(EE / 8, 4), blk>>>(Vr1, edges, alpha, ssum, att1, D1);

    gelu_kernel<<<4096, 256>>>(att1, gel, (long)TT * NN * F1);
    {
        dim3 g(F1 / GBN, mtiles, TT);
        gemm_tf32_kernel<<<g, blk, GEMM_SMEM_BYTES>>>(gel, Wa1, ba1, h1, NN, F1, F1,
                                (long)NN * F1, (long)F1 * F1, (long)NN * F1, F1);
    }

    // ===================== Layer 2 =====================
    {
        dim3 g(F2 / GBN, mtiles, TT);
        gemm_tf32_kernel<<<g, blk, GEMM_SMEM_BYTES>>>(h1, Wk2, bk2, K2, NN, F2, F1,
                                (long)NN * F1, (long)F1 * F2, (long)NN * F2, F2);
        gemm_tf32_kernel<<<g, blk, GEMM_SMEM_BYTES>>>(h1, Wq2, bq2, Q2, NN, F2, F1,
                                (long)NN * F1, (long)F1 * F2, (long)NN * F2, F2);
        gemm_tf32_kernel<<<g, blk, GEMM_SMEM_BYTES>>>(h1, Wv2, bv2, V2, NN, F2, F1,
                                (long)NN * F1, (long)F1 * F2, (long)NN * F2, F2);
    }
    {
        dim3 g((D2 + GBN - 1) / GBN, mtiles, 32);
        rel_gemm_tf32_kernel<<<g, blk, GEMM_SMEM_BYTES>>>(K2, arel2, Kr2, D2);
        rel_gemm_tf32_kernel<<<g, blk, GEMM_SMEM_BYTES>>>(V2, mrel2, Vr2, D2);
    }
    fill_kernel<<<2048, 256>>>(smax, -INFINITY, 4L * NN * HH);
    fill_kernel<<<2048, 256>>>(ssum, 0.f, 4L * NN * HH);
    fill_kernel<<<4096, 256>>>(att2, 0.f, (long)TT * NN * F2);

    attn_logits_kernel<<<dim3(EE / 8, 4), blk>>>(Q2, Kr2, edges, prel2, alpha, smax, D2);
    attn_expsum_kernel<<<(4 * EE * HH + 255) / 256, blk>>>(edges, alpha, smax, ssum);
    attn_agg_kernel<<<dim3(EE / 8, 4), blk>>>(Vr2, edges, alpha, ssum, att2, D2);

    gelu_kernel<<<4096, 256>>>(att2, gel, (long)TT * NN * F2);
    {
        dim3 g(F2 / GBN, mtiles, TT);
        gemm_tf32_kernel<<<g, blk, GEMM_SMEM_BYTES>>>(gel, Wa2, ba2, h2, NN, F2, F2,
                                (long)NN * F2, (long)F2 * F2, (long)NN * F2, F2);
    }

    // ===================== Final linear + softmax =====================
    final_softmax_kernel<<<(TT * NN * 32 + 255) / 256, blk>>>(h2, Wlin, blin, (float*)d_out);
}

// round 15
// speedup vs baseline: 3.7923x; 1.1811x over previous
#include <cuda_runtime.h>
#include <math.h>

#define TT   2
#define NN   10000
#define EE   60000
#define HH   8
#define FIN  2048
#define F1   1024
#define D1   128
#define F2   512
#define D2   64
#define NOUT 8

// ---------------- device scratch (no runtime allocation allowed) ----------------
__device__ float g_K1[TT*NN*F1];
__device__ float g_Q1[TT*NN*F1];
__device__ float g_V1[TT*NN*F1];
__device__ float g_Krel1[4*NN*F1];
__device__ float g_Vrel1[4*NN*F1];
__device__ float g_gel[TT*NN*F1];
__device__ float g_h1[TT*NN*F1];
__device__ float g_K2[TT*NN*F2];
__device__ float g_Q2[TT*NN*F2];
__device__ float g_V2[TT*NN*F2];
__device__ float g_Krel2[4*NN*F2];
__device__ float g_Vrel2[4*NN*F2];
__device__ float g_h2[TT*NN*F2];
// CSR by destination, per edge type
__device__ int g_cnt[4*NN];          // counts, then reused as scatter cursor
__device__ int g_off[4*(NN+1)];
__device__ int g_srcs[4*EE];

// =================== TF32 tensor-core GEMM (unchanged, known-good) ===================
#define GBM 128
#define GBN 128
#define GBK 32
#define APAD 4
#define BPAD 4
#define AS_STRIDE (GBK + APAD)
#define BS_STRIDE (GBN + BPAD)
#define AS_ELEMS (GBM * AS_STRIDE)
#define BS_ELEMS (GBK * BS_STRIDE)
#define GEMM_SMEM_BYTES ((2 * AS_ELEMS + 2 * BS_ELEMS) * 4)

__device__ __forceinline__ void cp16(unsigned* dst_smem, const float* src, bool pred)
{
    unsigned d = (unsigned)__cvta_generic_to_shared(dst_smem);
    int sz = pred ? 16 : 0;   // src-size 0 => zero-fill, no global access
    asm volatile("cp.async.cg.shared.global [%0], [%1], 16, %2;\n"
                 :: "r"(d), "l"(src), "r"(sz));
}

__device__ __forceinline__ void mma_tf32(float c[4],
                                         unsigned a0, unsigned a1, unsigned a2, unsigned a3,
                                         unsigned b0, unsigned b1)
{
    asm volatile(
        "mma.sync.aligned.m16n8k8.row.col.f32.tf32.tf32.f32 "
        "{%0,%1,%2,%3}, {%4,%5,%6,%7}, {%8,%9}, {%0,%1,%2,%3};\n"
        : "+f"(c[0]), "+f"(c[1]), "+f"(c[2]), "+f"(c[3])
        : "r"(a0), "r"(a1), "r"(a2), "r"(a3), "r"(b0), "r"(b1));
}

__device__ __forceinline__ void gemm_tf32_core(
    unsigned* smem,
    const float* __restrict__ A, long lda,
    const float* __restrict__ B, long ldb,
    const float* __restrict__ bias,
    float* __restrict__ C, long ldc,
    int M, int N, int K)
{
    unsigned* smA = smem;
    unsigned* smB = smem + 2 * AS_ELEMS;

    const int tid  = threadIdx.x;
    const int lane = tid & 31;
    const int wid  = tid >> 5;
    const int wm   = wid & 1;
    const int wn   = wid >> 1;
    const int grp  = lane >> 2;
    const int tg   = lane & 3;

    const int m0 = blockIdx.y * GBM;
    const int n0 = blockIdx.x * GBN;

    float acc[4][4][4];
#pragma unroll
    for (int mt = 0; mt < 4; mt++)
#pragma unroll
        for (int nt = 0; nt < 4; nt++)
#pragma unroll
            for (int i = 0; i < 4; i++) acc[mt][nt][i] = 0.f;

    const int niter = K / GBK;

    auto issue = [&](int k0, int buf) {
        unsigned* Asb = smA + buf * AS_ELEMS;
        unsigned* Bsb = smB + buf * BS_ELEMS;
#pragma unroll
        for (int j = 0; j < 4; j++) {                 // A: 128x32 = 1024 float4
            int i = tid + j * 256;
            int r = i >> 3, kc = (i & 7) * 4;
            int m = m0 + r;
            cp16(Asb + r * AS_STRIDE + kc, A + (long)m * lda + k0 + kc, m < M);
        }
#pragma unroll
        for (int j = 0; j < 4; j++) {                 // B: 32x128 = 1024 float4
            int i = tid + j * 256;
            int r = i >> 5, nc = (i & 31) * 4;
            int n = n0 + nc;
            cp16(Bsb + r * BS_STRIDE + nc, B + (long)(k0 + r) * ldb + n, n < N);
        }
        asm volatile("cp.async.commit_group;\n");
    };

    issue(0, 0);

    for (int it = 0; it < niter; ++it) {
        if (it + 1 < niter) {
            issue((it + 1) * GBK, (it + 1) & 1);
            asm volatile("cp.async.wait_group 1;\n");
        } else {
            asm volatile("cp.async.wait_group 0;\n");
        }
        __syncthreads();

        unsigned* Asb = smA + (it & 1) * AS_ELEMS;
        unsigned* Bsb = smB + (it & 1) * BS_ELEMS;

#pragma unroll
        for (int ks = 0; ks < GBK / 8; ks++) {
            const int kk = ks * 8;
            unsigned a[4][4], b[4][2];
#pragma unroll
            for (int mt = 0; mt < 4; mt++) {
                int r = wm * 64 + mt * 16 + grp;
                a[mt][0] = Asb[r * AS_STRIDE + kk + tg];
                a[mt][1] = Asb[(r + 8) * AS_STRIDE + kk + tg];
                a[mt][2] = Asb[r * AS_STRIDE + kk + tg + 4];
                a[mt][3] = Asb[(r + 8) * AS_STRIDE + kk + tg + 4];
            }
#pragma unroll
            for (int nt = 0; nt < 4; nt++) {
                int c = wn * 32 + nt * 8 + grp;
                b[nt][0] = Bsb[(kk + tg) * BS_STRIDE + c];
                b[nt][1] = Bsb[(kk + tg + 4) * BS_STRIDE + c];
            }
#pragma unroll
            for (int mt = 0; mt < 4; mt++)
#pragma unroll
                for (int nt = 0; nt < 4; nt++)
                    mma_tf32(acc[mt][nt], a[mt][0], a[mt][1], a[mt][2], a[mt][3],
                             b[nt][0], b[nt][1]);
        }
        __syncthreads();
    }

#pragma unroll
    for (int mt = 0; mt < 4; mt++) {
        int r0 = m0 + wm * 64 + mt * 16 + grp;
#pragma unroll
        for (int nt = 0; nt < 4; nt++) {
            int col = n0 + wn * 32 + nt * 8 + tg * 2;
            if (col >= N) continue;
            float bx = 0.f, by = 0.f;
            if (bias) { bx = bias[col]; by = bias[col + 1]; }
            if (r0 < M) {
                float2 v = make_float2(acc[mt][nt][0] + bx, acc[mt][nt][1] + by);
                *(float2*)(C + (long)r0 * ldc + col) = v;
            }
            if (r0 + 8 < M) {
                float2 v = make_float2(acc[mt][nt][2] + bx, acc[mt][nt][3] + by);
                *(float2*)(C + (long)(r0 + 8) * ldc + col) = v;
            }
        }
    }
}

__global__ __launch_bounds__(256, 2)
void gemm_tf32_kernel(const float* __restrict__ A, const float* __restrict__ B,
                      const float* __restrict__ bias, float* __restrict__ C,
                      int M, int N, int K,
                      long sA, long sB, long sC, long sBias)
{
    extern __shared__ unsigned smem_u[];
    int bz = blockIdx.z;
    gemm_tf32_core(smem_u,
                   A + (long)bz * sA, K,
                   B + (long)bz * sB, N,
                   bias + (long)bz * sBias,
                   C + (long)bz * sC, N,
                   M, N, K);
}

__global__ __launch_bounds__(256, 2)
void rel_gemm_tf32_kernel(const float* __restrict__ KQV,
                          const float* __restrict__ rel,
                          float* __restrict__ outp,
                          int D)
{
    extern __shared__ unsigned smem_u[];
    int z = blockIdx.z;            // 0..31
    int e = z >> 3;
    int h = z & 7;
    int st = e >> 1;
    int HD = HH * D;
    gemm_tf32_core(smem_u,
                   KQV + (long)st * NN * HD + h * D, HD,
                   rel + ((long)e * HH + h) * (long)D * D, D,
                   nullptr,
                   outp + (long)e * NN * HD + h * D, HD,
                   NN, D, D);
}

// =================== CSR build (by destination, per edge type) ===================
__global__ void zero_int_kernel(int* __restrict__ p, int n)
{
    int i = blockIdx.x * blockDim.x + threadIdx.x;
    if (i < n) p[i] = 0;
}

__global__ void csr_count_kernel(const int* __restrict__ e0, const int* __restrict__ e1,
                                 const int* __restrict__ e2, const int* __restrict__ e3,
                                 int* __restrict__ cnt)
{
    int i = blockIdx.x * blockDim.x + threadIdx.x;
    if (i >= 4 * EE) return;
    int e = i / EE, idx = i % EE;
    const int* p = (e == 0) ? e0 : (e == 1) ? e1 : (e == 2) ? e2 : e3;
    int dst = p[EE + idx];
    atomicAdd(&cnt[e * NN + dst], 1);
}

// one block (256 threads) per edge type: exclusive scan of counts -> offsets, zero counts
__global__ void csr_scan_kernel(int* __restrict__ cnt, int* __restrict__ off)
{
    const int C = (NN + 255) / 256;   // 40
    int e = blockIdx.x;
    int t = threadIdx.x;
    int base = t * C;
    int sum = 0;
    for (int j = 0; j < C; j++) {
        int i = base + j;
        if (i < NN) sum += cnt[e * NN + i];
    }
    __shared__ int sh[256];
    sh[t] = sum;
    __syncthreads();
    for (int o = 1; o < 256; o <<= 1) {
        int v = (t >= o) ? sh[t - o] : 0;
        __syncthreads();
        sh[t] += v;
        __syncthreads();
    }
    int run = sh[t] - sum;      // exclusive prefix
    for (int j = 0; j < C; j++) {
        int i = base + j;
        if (i < NN) {
            off[e * (NN + 1) + i] = run;
            run += cnt[e * NN + i];
            cnt[e * NN + i] = 0;    // becomes scatter cursor
        }
    }
    if (t == 0) off[e * (NN + 1) + NN] = EE;
}

__global__ void csr_scatter_kernel(const int* __restrict__ e0, const int* __restrict__ e1,
                                   const int* __restrict__ e2, const int* __restrict__ e3,
                                   const int* __restrict__ off, int* __restrict__ cur,
                                   int* __restrict__ srcs)
{
    int i = blockIdx.x * blockDim.x + threadIdx.x;
    if (i >= 4 * EE) return;
    int e = i / EE, idx = i % EE;
    const int* p = (e == 0) ? e0 : (e == 1) ? e1 : (e == 2) ? e2 : e3;
    int s = p[idx];
    int d = p[EE + idx];
    int pos = atomicAdd(&cur[e * NN + d], 1);
    srcs[e * EE + off[e * (NN + 1) + d] + pos] = s;
}

// =================== fused attention: online softmax + aggregation + GELU ===================
// One block per (node, dst-type). 128 threads; thread owns VPT = H*D/128 contiguous
// channels (all within one head); per-head reductions via width-16 shfl.
// Processes both incoming edge types (e = dt and e = dt+2) with separate softmax
// state, sums the two aggregates, applies exact GELU, writes output once.
template<int D>
__global__ __launch_bounds__(128)
void attn_fused_kernel(const float* __restrict__ Q,     // [TT,NN,H*D]
                       const float* __restrict__ Krel,  // [4,NN,H*D]
                       const float* __restrict__ Vrel,  // [4,NN,H*D]
                       const int* __restrict__ off,     // [4,NN+1]
                       const int* __restrict__ srcs,    // [4,EE]
                       const float* __restrict__ prel,  // [4,H]
                       float* __restrict__ gel)         // [TT,NN,H*D] (GELU applied)
{
    constexpr int HD  = HH * D;
    constexpr int VPT = HD / 128;       // 8 (D=128) or 4 (D=64)
    constexpr int NV4 = VPT / 4;

    const int n   = blockIdx.x;
    const int dt  = blockIdx.y;
    const int tid = threadIdx.x;
    const int c0  = tid * VPT;
    const int h   = c0 / D;

    float q[VPT];
    {
        const float4* q4 = (const float4*)(Q + ((long)dt * NN + n) * HD + c0);
#pragma unroll
        for (int u = 0; u < NV4; u++) {
            float4 v = q4[u];
            q[4*u+0] = v.x; q[4*u+1] = v.y; q[4*u+2] = v.z; q[4*u+3] = v.w;
        }
    }
    const float inv = rsqrtf((float)D);

    float outacc[VPT];
#pragma unroll
    for (int j = 0; j < VPT; j++) outacc[j] = 0.f;

#pragma unroll
    for (int pass = 0; pass < 2; pass++) {
        const int e   = dt + 2 * pass;          // edge types with dst type dt
        const int beg = off[e * (NN + 1) + n];
        const int end = off[e * (NN + 1) + n + 1];
        const float pr = prel[e * HH + h] * inv;
        const float* Kb = Krel + (long)e * NN * HD;
        const float* Vb = Vrel + (long)e * NN * HD;
        const int* sp = srcs + (long)e * EE;

        float m = -INFINITY, s = 0.f;
        float acc[VPT];
#pragma unroll
        for (int j = 0; j < VPT; j++) acc[j] = 0.f;

        for (int idx = beg; idx < end; idx++) {
            int src = sp[idx];
            const float4* k4 = (const float4*)(Kb + (long)src * HD + c0);
            const float4* v4 = (const float4*)(Vb + (long)src * HD + c0);
            float kv[VPT], vv[VPT];
#pragma unroll
            for (int u = 0; u < NV4; u++) {
                float4 a = k4[u];
                kv[4*u+0] = a.x; kv[4*u+1] = a.y; kv[4*u+2] = a.z; kv[4*u+3] = a.w;
                float4 b = v4[u];
                vv[4*u+0] = b.x; vv[4*u+1] = b.y; vv[4*u+2] = b.z; vv[4*u+3] = b.w;
            }
            float dotp = 0.f;
#pragma unroll
            for (int j = 0; j < VPT; j++) dotp += q[j] * kv[j];
#pragma unroll
            for (int o = 8; o; o >>= 1)
                dotp += __shfl_xor_sync(0xffffffffu, dotp, o, 16);
            float logit = dotp * pr;
            float mnew  = fmaxf(m, logit);
            float co    = __expf(m - mnew);      // 0 on first edge (m = -inf)
            float p     = __expf(logit - mnew);
            s = s * co + p;
#pragma unroll
            for (int j = 0; j < VPT; j++) acc[j] = acc[j] * co + p * vv[j];
            m = mnew;
        }
        if (s > 0.f) {
            float is = 1.f / s;
#pragma unroll
            for (int j = 0; j < VPT; j++) outacc[j] += acc[j] * is;
        }
    }

    float* o = gel + ((long)dt * NN + n) * HD + c0;
#pragma unroll
    for (int j = 0; j < VPT; j++) {
        float xv = outacc[j];
        o[j] = 0.5f * xv * (1.0f + erff(xv * 0.7071067811865476f));
    }
}

// ---------------- final: logits = h @ Wlin + blin; row softmax ----------------
__global__ void final_softmax_kernel(const float* __restrict__ h,    // [TT*NN, F2]
                                     const float* __restrict__ Wlin, // [F2, NOUT]
                                     const float* __restrict__ blin, // [NOUT]
                                     float* __restrict__ out)        // [TT*NN, NOUT]
{
    int row = (blockIdx.x * blockDim.x + threadIdx.x) >> 5;
    if (row >= TT * NN) return;
    int lane = threadIdx.x & 31;
    const float* hr = h + (long)row * F2;
    float acc[NOUT];
#pragma unroll
    for (int o = 0; o < NOUT; o++) acc[o] = 0.f;
    for (int f = lane; f < F2; f += 32) {
        float hv = hr[f];
#pragma unroll
        for (int o = 0; o < NOUT; o++) acc[o] += hv * Wlin[f * NOUT + o];
    }
#pragma unroll
    for (int o = 0; o < NOUT; o++)
#pragma unroll
        for (int s = 16; s; s >>= 1) acc[o] += __shfl_xor_sync(0xffffffffu, acc[o], s);
    if (lane == 0) {
        float vals[NOUT];
        float m = -INFINITY;
#pragma unroll
        for (int o = 0; o < NOUT; o++) { vals[o] = acc[o] + blin[o]; m = fmaxf(m, vals[o]); }
        float s = 0.f;
#pragma unroll
        for (int o = 0; o < NOUT; o++) { vals[o] = __expf(vals[o] - m); s += vals[o]; }
        float invs = 1.0f / s;
#pragma unroll
        for (int o = 0; o < NOUT; o++) out[(long)row * NOUT + o] = vals[o] * invs;
    }
}

// ---------------- host orchestration ----------------
static float* sym(const void* s)
{
    void* p = nullptr;
    cudaGetSymbolAddress(&p, (const void*)s);
    return (float*)p;
}

extern "C" void kernel_launch(void* const* d_in, const int* in_sizes, int n_in,
                              void* d_out, int out_size)
{
    const float* x     = (const float*)d_in[0];
    const int*   e0 = (const int*)d_in[1];
    const int*   e1 = (const int*)d_in[2];
    const int*   e2 = (const int*)d_in[3];
    const int*   e3 = (const int*)d_in[4];
    const float* Wk1 = (const float*)d_in[5];  const float* bk1 = (const float*)d_in[6];
    const float* Wq1 = (const float*)d_in[7];  const float* bq1 = (const float*)d_in[8];
    const float* Wv1 = (const float*)d_in[9];  const float* bv1 = (const float*)d_in[10];
    const float* Wa1 = (const float*)d_in[11]; const float* ba1 = (const float*)d_in[12];
    const float* arel1 = (const float*)d_in[13];
    const float* mrel1 = (const float*)d_in[14];
    const float* prel1 = (const float*)d_in[15];
    const float* Wk2 = (const float*)d_in[16]; const float* bk2 = (const float*)d_in[17];
    const float* Wq2 = (const float*)d_in[18]; const float* bq2 = (const float*)d_in[19];
    const float* Wv2 = (const float*)d_in[20]; const float* bv2 = (const float*)d_in[21];
    const float* Wa2 = (const float*)d_in[22]; const float* ba2 = (const float*)d_in[23];
    const float* arel2 = (const float*)d_in[24];
    const float* mrel2 = (const float*)d_in[25];
    const float* prel2 = (const float*)d_in[26];
    const float* Wlin  = (const float*)d_in[27];
    const float* blin  = (const float*)d_in[28];

    float* K1 = sym(g_K1);   float* Q1 = sym(g_Q1);   float* V1 = sym(g_V1);
    float* Kr1 = sym(g_Krel1); float* Vr1 = sym(g_Vrel1);
    float* gel = sym(g_gel); float* h1 = sym(g_h1);
    float* K2 = sym(g_K2);   float* Q2 = sym(g_Q2);   float* V2 = sym(g_V2);
    float* Kr2 = sym(g_Krel2); float* Vr2 = sym(g_Vrel2);
    float* h2 = sym(g_h2);
    int* cnt  = (int*)sym(g_cnt);
    int* off  = (int*)sym(g_off);
    int* srcs = (int*)sym(g_srcs);

    cudaFuncSetAttribute(gemm_tf32_kernel,
                         cudaFuncAttributeMaxDynamicSharedMemorySize, GEMM_SMEM_BYTES);
    cudaFuncSetAttribute(rel_gemm_tf32_kernel,
                         cudaFuncAttributeMaxDynamicSharedMemorySize, GEMM_SMEM_BYTES);

    dim3 blk(256);
    int mtiles = (NN + GBM - 1) / GBM;   // 79

    // ===================== CSR build (shared by both layers) =====================
    zero_int_kernel<<<(4 * NN + 255) / 256, 256>>>(cnt, 4 * NN);
    csr_count_kernel<<<(4 * EE + 255) / 256, 256>>>(e0, e1, e2, e3, cnt);
    csr_scan_kernel<<<4, 256>>>(cnt, off);
    csr_scatter_kernel<<<(4 * EE + 255) / 256, 256>>>(e0, e1, e2, e3, off, cnt, srcs);

    // ===================== Layer 1 =====================
    {
        dim3 g(F1 / GBN, mtiles, TT);
        gemm_tf32_kernel<<<g, blk, GEMM_SMEM_BYTES>>>(x, Wk1, bk1, K1, NN, F1, FIN,
                                (long)NN * FIN, (long)FIN * F1, (long)NN * F1, F1);
        gemm_tf32_kernel<<<g, blk, GEMM_SMEM_BYTES>>>(x, Wq1, bq1, Q1, NN, F1, FIN,
                                (long)NN * FIN, (long)FIN * F1, (long)NN * F1, F1);
        gemm_tf32_kernel<<<g, blk, GEMM_SMEM_BYTES>>>(x, Wv1, bv1, V1, NN, F1, FIN,
                                (long)NN * FIN, (long)FIN * F1, (long)NN * F1, F1);
    }
    {
        dim3 g((D1 + GBN - 1) / GBN, mtiles, 32);
        rel_gemm_tf32_kernel<<<g, blk, GEMM_SMEM_BYTES>>>(K1, arel1, Kr1, D1);
        rel_gemm_tf32_kernel<<<g, blk, GEMM_SMEM_BYTES>>>(V1, mrel1, Vr1, D1);
    }
    attn_fused_kernel<D1><<<dim3(NN, TT), 128>>>(Q1, Kr1, Vr1, off, srcs, prel1, gel);
    {
        dim3 g(F1 / GBN, mtiles, TT);
        gemm_tf32_kernel<<<g, blk, GEMM_SMEM_BYTES>>>(gel, Wa1, ba1, h1, NN, F1, F1,
                                (long)NN * F1, (long)F1 * F1, (long)NN * F1, F1);
    }

    // ===================== Layer 2 =====================
    {
        dim3 g(F2 / GBN, mtiles, TT);
        gemm_tf32_kernel<<<g, blk, GEMM_SMEM_BYTES>>>(h1, Wk2, bk2, K2, NN, F2, F1,
                                (long)NN * F1, (long)F1 * F2, (long)NN * F2, F2);
        gemm_tf32_kernel<<<g, blk, GEMM_SMEM_BYTES>>>(h1, Wq2, bq2, Q2, NN, F2, F1,
                                (long)NN * F1, (long)F1 * F2, (long)NN * F2, F2);
        gemm_tf32_kernel<<<g, blk, GEMM_SMEM_BYTES>>>(h1, Wv2, bv2, V2, NN, F2, F1,
                                (long)NN * F1, (long)F1 * F2, (long)NN * F2, F2);
    }
    {
        dim3 g((D2 + GBN - 1) / GBN, mtiles, 32);
        rel_gemm_tf32_kernel<<<g, blk, GEMM_SMEM_BYTES>>>(K2, arel2, Kr2, D2);
        rel_gemm_tf32_kernel<<<g, blk, GEMM_SMEM_BYTES>>>(V2, mrel2, Vr2, D2);
    }
    attn_fused_kernel<D2><<<dim3(NN, TT), 128>>>(Q2, Kr2, Vr2, off, srcs, prel2, gel);
    {
        dim3 g(F2 / GBN, mtiles, TT);
        gemm_tf32_kernel<<<g, blk, GEMM_SMEM_BYTES>>>(gel, Wa2, ba2, h2, NN, F2, F2,
                                (long)NN * F2, (long)F2 * F2, (long)NN * F2, F2);
    }

    // ===================== Final linear + softmax =====================
    final_softmax_kernel<<<(TT * NN * 32 + 255) / 256, blk>>>(h2, Wlin, blin, (float*)d_out);
}

// round 16
// speedup vs baseline: 6.4428x; 1.6989x over previous
#include <cuda_runtime.h>
#include <cuda_bf16.h>
#include <math.h>

#define TT   2
#define NN   10000
#define EE   60000
#define HH   8
#define FIN  2048
#define F1   1024
#define D1   128
#define F2   512
#define D2   64
#define NOUT 8

typedef __nv_bfloat16 bf16;

// ---------------- device scratch (no runtime allocation allowed) ----------------
// bf16 activation chain
__device__ bf16 gb_x  [TT*NN*FIN];
__device__ bf16 gb_K1 [TT*NN*F1];
__device__ bf16 gb_V1 [TT*NN*F1];
__device__ bf16 gb_gel1[TT*NN*F1];
__device__ bf16 gb_h1 [TT*NN*F1];
__device__ bf16 gb_K2 [TT*NN*F2];
__device__ bf16 gb_V2 [TT*NN*F2];
__device__ bf16 gb_gel2[TT*NN*F2];
__device__ bf16 gb_h2 [TT*NN*F2];
// fp32 attention operands
__device__ float g_Q1   [TT*NN*F1];
__device__ float g_Krel1[4*NN*F1];
__device__ float g_Vrel1[4*NN*F1];
__device__ float g_Q2   [TT*NN*F2];
__device__ float g_Krel2[4*NN*F2];
__device__ float g_Vrel2[4*NN*F2];
// transposed bf16 weights [.., N, K]
__device__ bf16 gb_Wk1t[TT*FIN*F1];
__device__ bf16 gb_Wq1t[TT*FIN*F1];
__device__ bf16 gb_Wv1t[TT*FIN*F1];
__device__ bf16 gb_Wa1t[TT*F1*F1];
__device__ bf16 gb_Wk2t[TT*F1*F2];
__device__ bf16 gb_Wq2t[TT*F1*F2];
__device__ bf16 gb_Wv2t[TT*F1*F2];
__device__ bf16 gb_Wa2t[TT*F2*F2];
__device__ bf16 gb_ar1t[4*HH*D1*D1];
__device__ bf16 gb_mr1t[4*HH*D1*D1];
__device__ bf16 gb_ar2t[4*HH*D2*D2];
__device__ bf16 gb_mr2t[4*HH*D2*D2];
// CSR by destination, per edge type
__device__ int g_cnt[4*NN];
__device__ int g_off[4*(NN+1)];
__device__ int g_srcs[4*EE];

// =================== bf16 tensor-core GEMM ===================
// Block tile 128x128x32(bf16 k), 256 threads = 8 warps (2M x 4N), warp tile 64x32.
// mma m16n8k16 bf16 -> fp32. ldmatrix fragment loads. 4-stage cp.async pipeline.
// Smem per stage: As 128x32 bf16 (8KB) + Bs 128x32 bf16 (8KB). 4 stages = 64KB.
#define GBK 32
#define STAGE_ELEMS 4096                 // 128*32 bf16 per tile
#define GEMM_SMEM_BYTES (4 * 2 * STAGE_ELEMS * 2)

__device__ __forceinline__ void cp16(void* dst_smem, const void* src, bool pred)
{
    unsigned d = (unsigned)__cvta_generic_to_shared(dst_smem);
    int sz = pred ? 16 : 0;   // src-size 0 => zero-fill, no global access
    asm volatile("cp.async.cg.shared.global [%0], [%1], 16, %2;\n"
                 :: "r"(d), "l"(src), "r"(sz));
}

__device__ __forceinline__ void ldm4(unsigned r[4], unsigned addr)
{
    asm volatile("ldmatrix.sync.aligned.m8n8.x4.shared.b16 {%0,%1,%2,%3}, [%4];\n"
                 : "=r"(r[0]), "=r"(r[1]), "=r"(r[2]), "=r"(r[3]) : "r"(addr));
}

__device__ __forceinline__ void mma_bf16(float c[4],
                                         unsigned a0, unsigned a1, unsigned a2, unsigned a3,
                                         unsigned b0, unsigned b1)
{
    asm volatile(
        "mma.sync.aligned.m16n8k16.row.col.f32.bf16.bf16.f32 "
        "{%0,%1,%2,%3}, {%4,%5,%6,%7}, {%8,%9}, {%0,%1,%2,%3};\n"
        : "+f"(c[0]), "+f"(c[1]), "+f"(c[2]), "+f"(c[3])
        : "r"(a0), "r"(a1), "r"(a2), "r"(a3), "r"(b0), "r"(b1));
}

// C[M,N] = A[M,K] @ Bt[N,K]^T (+bias). A,Bt bf16 row-major. K % 32 == 0.
template<bool OBF>
__device__ __forceinline__ void gemm_bf16_core(
    bf16* smem,
    const bf16* __restrict__ A, long lda,
    const bf16* __restrict__ Bt, long ldb,
    const float* __restrict__ bias,
    void* __restrict__ Cp, long ldc,
    int M, int N, int K)
{
    bf16* smA = smem;                         // 4 stages A
    bf16* smB = smem + 4 * STAGE_ELEMS;       // 4 stages B

    const int tid  = threadIdx.x;
    const int lane = tid & 31;
    const int wid  = tid >> 5;
    const int wm   = wid & 1;
    const int wn   = wid >> 1;
    const int grp  = lane >> 2;
    const int tg   = lane & 3;
    const int l15  = lane & 15;
    const int cb   = lane >> 4;               // 0/1: chunk half for ldmatrix
    const int sx   = (l15 >> 1) & 3;          // per-lane swizzle XOR (tile-invariant)

    const int m0 = blockIdx.y * 128;
    const int n0 = blockIdx.x * 128;

    float acc[4][4][4];
#pragma unroll
    for (int mt = 0; mt < 4; mt++)
#pragma unroll
        for (int nt = 0; nt < 4; nt++)
#pragma unroll
            for (int i = 0; i < 4; i++) acc[mt][nt][i] = 0.f;

    const int niter = K / GBK;

    auto issue = [&](int tile) {
        if (tile < niter) {
            const int k0 = tile * GBK;
            bf16* Asb = smA + (tile & 3) * STAGE_ELEMS;
            bf16* Bsb = smB + (tile & 3) * STAGE_ELEMS;
#pragma unroll
            for (int j = 0; j < 2; j++) {     // A: 128 rows x 4 chunks = 512
                int i = tid + j * 256;
                int r = i >> 2, c = i & 3;
                int sw = c ^ ((r >> 1) & 3);
                cp16(Asb + r * 32 + sw * 8, A + (long)(m0 + r) * lda + k0 + c * 8,
                     (m0 + r) < M);
            }
#pragma unroll
            for (int j = 0; j < 2; j++) {     // B: 128 n-rows x 4 chunks
                int i = tid + j * 256;
                int r = i >> 2, c = i & 3;
                int sw = c ^ ((r >> 1) & 3);
                cp16(Bsb + r * 32 + sw * 8, Bt + (long)(n0 + r) * ldb + k0 + c * 8,
                     (n0 + r) < N);
            }
        }
        asm volatile("cp.async.commit_group;\n");
    };

    issue(0); issue(1); issue(2);

    unsigned smA_u = (unsigned)__cvta_generic_to_shared(smA);
    unsigned smB_u = (unsigned)__cvta_generic_to_shared(smB);

    for (int it = 0; it < niter; ++it) {
        issue(it + 3);
        asm volatile("cp.async.wait_group 3;\n");
        __syncthreads();

        unsigned aU = smA_u + (it & 3) * (STAGE_ELEMS * 2);
        unsigned bU = smB_u + (it & 3) * (STAGE_ELEMS * 2);

#pragma unroll
        for (int slice = 0; slice < 2; slice++) {
            int cs = ((slice * 2 + cb) ^ sx);
            unsigned a[4][4], b[2][4];
#pragma unroll
            for (int mt = 0; mt < 4; mt++) {
                int r = wm * 64 + mt * 16 + l15;
                ldm4(a[mt], aU + (r * 32 + cs * 8) * 2);
            }
#pragma unroll
            for (int ntp = 0; ntp < 2; ntp++) {
                int r = wn * 32 + ntp * 16 + l15;
                ldm4(b[ntp], bU + (r * 32 + cs * 8) * 2);
            }
#pragma unroll
            for (int mt = 0; mt < 4; mt++)
#pragma unroll
                for (int nt = 0; nt < 4; nt++)
                    mma_bf16(acc[mt][nt],
                             a[mt][0], a[mt][1], a[mt][2], a[mt][3],
                             b[nt >> 1][nt & 1], b[nt >> 1][2 + (nt & 1)]);
        }
        __syncthreads();
    }

    // ---- epilogue: bias + store ----
#pragma unroll
    for (int mt = 0; mt < 4; mt++) {
        int r0 = m0 + wm * 64 + mt * 16 + grp;
#pragma unroll
        for (int nt = 0; nt < 4; nt++) {
            int col = n0 + wn * 32 + nt * 8 + tg * 2;
            if (col >= N) continue;
            float bx = 0.f, by = 0.f;
            if (bias) { bx = bias[col]; by = bias[col + 1]; }
            float v00 = acc[mt][nt][0] + bx, v01 = acc[mt][nt][1] + by;
            float v10 = acc[mt][nt][2] + bx, v11 = acc[mt][nt][3] + by;
            if (OBF) {
                bf16* C = (bf16*)Cp;
                if (r0 < M)
                    *(__nv_bfloat162*)(C + (long)r0 * ldc + col) =
                        __floats2bfloat162_rn(v00, v01);
                if (r0 + 8 < M)
                    *(__nv_bfloat162*)(C + (long)(r0 + 8) * ldc + col) =
                        __floats2bfloat162_rn(v10, v11);
            } else {
                float* C = (float*)Cp;
                if (r0 < M)
                    *(float2*)(C + (long)r0 * ldc + col) = make_float2(v00, v01);
                if (r0 + 8 < M)
                    *(float2*)(C + (long)(r0 + 8) * ldc + col) = make_float2(v10, v11);
            }
        }
    }
}

template<bool OBF>
__global__ __launch_bounds__(256, 2)
void gemm_bf16_kernel(const bf16* __restrict__ A, const bf16* __restrict__ Bt,
                      const float* __restrict__ bias, void* __restrict__ C,
                      int M, int N, int K,
                      long sA, long sB, long sC, long sBias)
{
    extern __shared__ bf16 smem_b[];
    int bz = blockIdx.z;
    gemm_bf16_core<OBF>(smem_b,
                        A + (long)bz * sA, K,
                        Bt + (long)bz * sB, K,
                        bias + (long)bz * sBias,
                        OBF ? (void*)((bf16*)C + (long)bz * sC)
                            : (void*)((float*)C + (long)bz * sC),
                        N, M, N, K);
}

// out[e,n,h,:] = KQV[st,n,h,:] @ relT[e,h]^T   (relT pre-transposed [D(n)][D(k)])
__global__ __launch_bounds__(256, 2)
void rel_gemm_bf16_kernel(const bf16* __restrict__ KQV,
                          const bf16* __restrict__ relT,
                          float* __restrict__ outp,
                          int D)
{
    extern __shared__ bf16 smem_b[];
    int z = blockIdx.z;            // 0..31
    int e = z >> 3;
    int h = z & 7;
    int st = e >> 1;
    int HD = HH * D;
    gemm_bf16_core<false>(smem_b,
                          KQV + (long)st * NN * HD + h * D, HD,
                          relT + ((long)e * HH + h) * (long)D * D, D,
                          nullptr,
                          outp + (long)e * NN * HD + h * D, HD,
                          NN, D, D);
}

// =================== conversions ===================
__global__ void cvt_bf16_kernel(const float* __restrict__ in, bf16* __restrict__ out, long n4)
{
    long i = (long)blockIdx.x * blockDim.x + threadIdx.x;
    if (i >= n4) return;
    float4 v = ((const float4*)in)[i];
    ((__nv_bfloat162*)out)[2*i]   = __floats2bfloat162_rn(v.x, v.y);
    ((__nv_bfloat162*)out)[2*i+1] = __floats2bfloat162_rn(v.z, v.w);
}

// in [z][K][N] fp32 -> out [z][N][K] bf16. K,N multiples of 32. block (32,8)
__global__ void transpose_cvt_kernel(const float* __restrict__ in, bf16* __restrict__ out,
                                     int K, int N)
{
    __shared__ float t[32][33];
    long zoff = (long)blockIdx.z * K * N;
    int n0 = blockIdx.x * 32, k0 = blockIdx.y * 32;
    int tx = threadIdx.x, ty = threadIdx.y;
#pragma unroll
    for (int s = 0; s < 4; s++)
        t[ty + 8*s][tx] = in[zoff + (long)(k0 + ty + 8*s) * N + n0 + tx];
    __syncthreads();
#pragma unroll
    for (int s = 0; s < 4; s++)
        out[zoff + (long)(n0 + ty + 8*s) * K + k0 + tx] =
            __float2bfloat16(t[tx][ty + 8*s]);
}

// =================== CSR build (by destination, per edge type) ===================
__global__ void zero_int_kernel(int* __restrict__ p, int n)
{
    int i = blockIdx.x * blockDim.x + threadIdx.x;
    if (i < n) p[i] = 0;
}

__global__ void csr_count_kernel(const int* __restrict__ e0, const int* __restrict__ e1,
                                 const int* __restrict__ e2, const int* __restrict__ e3,
                                 int* __restrict__ cnt)
{
    int i = blockIdx.x * blockDim.x + threadIdx.x;
    if (i >= 4 * EE) return;
    int e = i / EE, idx = i % EE;
    const int* p = (e == 0) ? e0 : (e == 1) ? e1 : (e == 2) ? e2 : e3;
    int dst = p[EE + idx];
    atomicAdd(&cnt[e * NN + dst], 1);
}

__global__ void csr_scan_kernel(int* __restrict__ cnt, int* __restrict__ off)
{
    const int C = (NN + 255) / 256;
    int e = blockIdx.x;
    int t = threadIdx.x;
    int base = t * C;
    int sum = 0;
    for (int j = 0; j < C; j++) {
        int i = base + j;
        if (i < NN) sum += cnt[e * NN + i];
    }
    __shared__ int sh[256];
    sh[t] = sum;
    __syncthreads();
    for (int o = 1; o < 256; o <<= 1) {
        int v = (t >= o) ? sh[t - o] : 0;
        __syncthreads();
        sh[t] += v;
        __syncthreads();
    }
    int run = sh[t] - sum;
    for (int j = 0; j < C; j++) {
        int i = base + j;
        if (i < NN) {
            off[e * (NN + 1) + i] = run;
            run += cnt[e * NN + i];
            cnt[e * NN + i] = 0;
        }
    }
    if (t == 0) off[e * (NN + 1) + NN] = EE;
}

__global__ void csr_scatter_kernel(const int* __restrict__ e0, const int* __restrict__ e1,
                                   const int* __restrict__ e2, const int* __restrict__ e3,
                                   const int* __restrict__ off, int* __restrict__ cur,
                                   int* __restrict__ srcs)
{
    int i = blockIdx.x * blockDim.x + threadIdx.x;
    if (i >= 4 * EE) return;
    int e = i / EE, idx = i % EE;
    const int* p = (e == 0) ? e0 : (e == 1) ? e1 : (e == 2) ? e2 : e3;
    int s = p[idx];
    int d = p[EE + idx];
    int pos = atomicAdd(&cur[e * NN + d], 1);
    srcs[e * EE + off[e * (NN + 1) + d] + pos] = s;
}

// =================== fused attention: online softmax + agg + GELU -> bf16 ===================
template<int D>
__global__ __launch_bounds__(128)
void attn_fused_kernel(const float* __restrict__ Q,     // [TT,NN,H*D]
                       const float* __restrict__ Krel,  // [4,NN,H*D]
                       const float* __restrict__ Vrel,  // [4,NN,H*D]
                       const int* __restrict__ off,     // [4,NN+1]
                       const int* __restrict__ srcs,    // [4,EE]
                       const float* __restrict__ prel,  // [4,H]
                       bf16* __restrict__ gel)          // [TT,NN,H*D] (GELU applied)
{
    constexpr int HD  = HH * D;
    constexpr int VPT = HD / 128;
    constexpr int NV4 = VPT / 4;

    const int n   = blockIdx.x;
    const int dt  = blockIdx.y;
    const int tid = threadIdx.x;
    const int c0  = tid * VPT;
    const int h   = c0 / D;

    float q[VPT];
    {
        const float4* q4 = (const float4*)(Q + ((long)dt * NN + n) * HD + c0);
#pragma unroll
        for (int u = 0; u < NV4; u++) {
            float4 v = q4[u];
            q[4*u+0] = v.x; q[4*u+1] = v.y; q[4*u+2] = v.z; q[4*u+3] = v.w;
        }
    }
    const float inv = rsqrtf((float)D);

    float outacc[VPT];
#pragma unroll
    for (int j = 0; j < VPT; j++) outacc[j] = 0.f;

#pragma unroll
    for (int pass = 0; pass < 2; pass++) {
        const int e   = dt + 2 * pass;
        const int beg = off[e * (NN + 1) + n];
        const int end = off[e * (NN + 1) + n + 1];
        const float pr = prel[e * HH + h] * inv;
        const float* Kb = Krel + (long)e * NN * HD;
        const float* Vb = Vrel + (long)e * NN * HD;
        const int* sp = srcs + (long)e * EE;

        float m = -INFINITY, s = 0.f;
        float acc[VPT];
#pragma unroll
        for (int j = 0; j < VPT; j++) acc[j] = 0.f;

        for (int idx = beg; idx < end; idx++) {
            int src = sp[idx];
            const float4* k4 = (const float4*)(Kb + (long)src * HD + c0);
            const float4* v4 = (const float4*)(Vb + (long)src * HD + c0);
            float kv[VPT], vv[VPT];
#pragma unroll
            for (int u = 0; u < NV4; u++) {
                float4 a = k4[u];
                kv[4*u+0] = a.x; kv[4*u+1] = a.y; kv[4*u+2] = a.z; kv[4*u+3] = a.w;
                float4 b = v4[u];
                vv[4*u+0] = b.x; vv[4*u+1] = b.y; vv[4*u+2] = b.z; vv[4*u+3] = b.w;
            }
            float dotp = 0.f;
#pragma unroll
            for (int j = 0; j < VPT; j++) dotp += q[j] * kv[j];
#pragma unroll
            for (int o = 8; o; o >>= 1)
                dotp += __shfl_xor_sync(0xffffffffu, dotp, o, 16);
            float logit = dotp * pr;
            float mnew  = fmaxf(m, logit);
            float co    = __expf(m - mnew);
            float p     = __expf(logit - mnew);
            s = s * co + p;
#pragma unroll
            for (int j = 0; j < VPT; j++) acc[j] = acc[j] * co + p * vv[j];
            m = mnew;
        }
        if (s > 0.f) {
            float is = 1.f / s;
#pragma unroll
            for (int j = 0; j < VPT; j++) outacc[j] += acc[j] * is;
        }
    }

    __nv_bfloat162* o2 = (__nv_bfloat162*)(gel + ((long)dt * NN + n) * HD + c0);
#pragma unroll
    for (int j = 0; j < VPT; j += 2) {
        float x0 = outacc[j], x1 = outacc[j+1];
        float g0 = 0.5f * x0 * (1.0f + erff(x0 * 0.7071067811865476f));
        float g1 = 0.5f * x1 * (1.0f + erff(x1 * 0.7071067811865476f));
        o2[j >> 1] = __floats2bfloat162_rn(g0, g1);
    }
}

// ---------------- final: logits = h @ Wlin + blin; row softmax ----------------
__global__ void final_softmax_kernel(const bf16* __restrict__ h,    // [TT*NN, F2]
                                     const float* __restrict__ Wlin,// [F2, NOUT]
                                     const float* __restrict__ blin,// [NOUT]
                                     float* __restrict__ out)       // [TT*NN, NOUT]
{
    int row = (blockIdx.x * blockDim.x + threadIdx.x) >> 5;
    if (row >= TT * NN) return;
    int lane = threadIdx.x & 31;
    const bf16* hr = h + (long)row * F2;
    float acc[NOUT];
#pragma unroll
    for (int o = 0; o < NOUT; o++) acc[o] = 0.f;
    for (int f = lane; f < F2; f += 32) {
        float hv = __bfloat162float(hr[f]);
#pragma unroll
        for (int o = 0; o < NOUT; o++) acc[o] += hv * Wlin[f * NOUT + o];
    }
#pragma unroll
    for (int o = 0; o < NOUT; o++)
#pragma unroll
        for (int s = 16; s; s >>= 1) acc[o] += __shfl_xor_sync(0xffffffffu, acc[o], s);
    if (lane == 0) {
        float vals[NOUT];
        float m = -INFINITY;
#pragma unroll
        for (int o = 0; o < NOUT; o++) { vals[o] = acc[o] + blin[o]; m = fmaxf(m, vals[o]); }
        float s = 0.f;
#pragma unroll
        for (int o = 0; o < NOUT; o++) { vals[o] = __expf(vals[o] - m); s += vals[o]; }
        float invs = 1.0f / s;
#pragma unroll
        for (int o = 0; o < NOUT; o++) out[(long)row * NOUT + o] = vals[o] * invs;
    }
}

// ---------------- host orchestration ----------------
static void* symv(const void* s)
{
    void* p = nullptr;
    cudaGetSymbolAddress(&p, (const void*)s);
    return p;
}

extern "C" void kernel_launch(void* const* d_in, const int* in_sizes, int n_in,
                              void* d_out, int out_size)
{
    const float* x  = (const float*)d_in[0];
    const int* e0 = (const int*)d_in[1];
    const int* e1 = (const int*)d_in[2];
    const int* e2 = (const int*)d_in[3];
    const int* e3 = (const int*)d_in[4];
    const float* Wk1 = (const float*)d_in[5];  const float* bk1 = (const float*)d_in[6];
    const float* Wq1 = (const float*)d_in[7];  const float* bq1 = (const float*)d_in[8];
    const float* Wv1 = (const float*)d_in[9];  const float* bv1 = (const float*)d_in[10];
    const float* Wa1 = (const float*)d_in[11]; const float* ba1 = (const float*)d_in[12];
    const float* arel1 = (const float*)d_in[13];
    const float* mrel1 = (const float*)d_in[14];
    const float* prel1 = (const float*)d_in[15];
    const float* Wk2 = (const float*)d_in[16]; const float* bk2 = (const float*)d_in[17];
    const float* Wq2 = (const float*)d_in[18]; const float* bq2 = (const float*)d_in[19];
    const float* Wv2 = (const float*)d_in[20]; const float* bv2 = (const float*)d_in[21];
    const float* Wa2 = (const float*)d_in[22]; const float* ba2 = (const float*)d_in[23];
    const float* arel2 = (const float*)d_in[24];
    const float* mrel2 = (const float*)d_in[25];
    const float* prel2 = (const float*)d_in[26];
    const float* Wlin  = (const float*)d_in[27];
    const float* blin  = (const float*)d_in[28];

    bf16* xb   = (bf16*)symv(gb_x);
    bf16* K1b  = (bf16*)symv(gb_K1);  bf16* V1b = (bf16*)symv(gb_V1);
    bf16* gel1 = (bf16*)symv(gb_gel1); bf16* h1b = (bf16*)symv(gb_h1);
    bf16* K2b  = (bf16*)symv(gb_K2);  bf16* V2b = (bf16*)symv(gb_V2);
    bf16* gel2 = (bf16*)symv(gb_gel2); bf16* h2b = (bf16*)symv(gb_h2);
    float* Q1  = (float*)symv(g_Q1);
    float* Kr1 = (float*)symv(g_Krel1); float* Vr1 = (float*)symv(g_Vrel1);
    float* Q2  = (float*)symv(g_Q2);
    float* Kr2 = (float*)symv(g_Krel2); float* Vr2 = (float*)symv(g_Vrel2);
    bf16* Wk1t = (bf16*)symv(gb_Wk1t); bf16* Wq1t = (bf16*)symv(gb_Wq1t);
    bf16* Wv1t = (bf16*)symv(gb_Wv1t); bf16* Wa1t = (bf16*)symv(gb_Wa1t);
    bf16* Wk2t = (bf16*)symv(gb_Wk2t); bf16* Wq2t = (bf16*)symv(gb_Wq2t);
    bf16* Wv2t = (bf16*)symv(gb_Wv2t); bf16* Wa2t = (bf16*)symv(gb_Wa2t);
    bf16* ar1t = (bf16*)symv(gb_ar1t); bf16* mr1t = (bf16*)symv(gb_mr1t);
    bf16* ar2t = (bf16*)symv(gb_ar2t); bf16* mr2t = (bf16*)symv(gb_mr2t);
    int* cnt  = (int*)symv(g_cnt);
    int* off  = (int*)symv(g_off);
    int* srcs = (int*)symv(g_srcs);

    cudaFuncSetAttribute(gemm_bf16_kernel<true>,
                         cudaFuncAttributeMaxDynamicSharedMemorySize, GEMM_SMEM_BYTES);
    cudaFuncSetAttribute(gemm_bf16_kernel<false>,
                         cudaFuncAttributeMaxDynamicSharedMemorySize, GEMM_SMEM_BYTES);
    cudaFuncSetAttribute(rel_gemm_bf16_kernel,
                         cudaFuncAttributeMaxDynamicSharedMemorySize, GEMM_SMEM_BYTES);

    dim3 blk(256);
    dim3 tb(32, 8);
    const int mtiles = (NN + 127) / 128;   // 79

    // ---- conversions (weights + input) ----
    {
        long n4 = (long)TT * NN * FIN / 4;
        cvt_bf16_kernel<<<(unsigned)((n4 + 255) / 256), 256>>>(x, xb, n4);
        transpose_cvt_kernel<<<dim3(F1/32, FIN/32, TT), tb>>>(Wk1, Wk1t, FIN, F1);
        transpose_cvt_kernel<<<dim3(F1/32, FIN/32, TT), tb>>>(Wq1, Wq1t, FIN, F1);
        transpose_cvt_kernel<<<dim3(F1/32, FIN/32, TT), tb>>>(Wv1, Wv1t, FIN, F1);
        transpose_cvt_kernel<<<dim3(F1/32, F1/32, TT),  tb>>>(Wa1, Wa1t, F1, F1);
        transpose_cvt_kernel<<<dim3(F2/32, F1/32, TT),  tb>>>(Wk2, Wk2t, F1, F2);
        transpose_cvt_kernel<<<dim3(F2/32, F1/32, TT),  tb>>>(Wq2, Wq2t, F1, F2);
        transpose_cvt_kernel<<<dim3(F2/32, F1/32, TT),  tb>>>(Wv2, Wv2t, F1, F2);
        transpose_cvt_kernel<<<dim3(F2/32, F2/32, TT),  tb>>>(Wa2, Wa2t, F2, F2);
        transpose_cvt_kernel<<<dim3(D1/32, D1/32, 32),  tb>>>(arel1, ar1t, D1, D1);
        transpose_cvt_kernel<<<dim3(D1/32, D1/32, 32),  tb>>>(mrel1, mr1t, D1, D1);
        transpose_cvt_kernel<<<dim3(D2/32, D2/32, 32),  tb>>>(arel2, ar2t, D2, D2);
        transpose_cvt_kernel<<<dim3(D2/32, D2/32, 32),  tb>>>(mrel2, mr2t, D2, D2);
    }

    // ---- CSR build ----
    zero_int_kernel<<<(4 * NN + 255) / 256, 256>>>(cnt, 4 * NN);
    csr_count_kernel<<<(4 * EE + 255) / 256, 256>>>(e0, e1, e2, e3, cnt);
    csr_scan_kernel<<<4, 256>>>(cnt, off);
    csr_scatter_kernel<<<(4 * EE + 255) / 256, 256>>>(e0, e1, e2, e3, off, cnt, srcs);

    // ===================== Layer 1 =====================
    {
        dim3 g(F1 / 128, mtiles, TT);
        gemm_bf16_kernel<true><<<g, blk, GEMM_SMEM_BYTES>>>(xb, Wk1t, bk1, K1b,
            NN, F1, FIN, (long)NN*FIN, (long)FIN*F1, (long)NN*F1, F1);
        gemm_bf16_kernel<false><<<g, blk, GEMM_SMEM_BYTES>>>(xb, Wq1t, bq1, Q1,
            NN, F1, FIN, (long)NN*FIN, (long)FIN*F1, (long)NN*F1, F1);
        gemm_bf16_kernel<true><<<g, blk, GEMM_SMEM_BYTES>>>(xb, Wv1t, bv1, V1b,
            NN, F1, FIN, (long)NN*FIN, (long)FIN*F1, (long)NN*F1, F1);
    }
    {
        dim3 g(1, mtiles, 32);
        rel_gemm_bf16_kernel<<<g, blk, GEMM_SMEM_BYTES>>>(K1b, ar1t, Kr1, D1);
        rel_gemm_bf16_kernel<<<g, blk, GEMM_SMEM_BYTES>>>(V1b, mr1t, Vr1, D1);
    }
    attn_fused_kernel<D1><<<dim3(NN, TT), 128>>>(Q1, Kr1, Vr1, off, srcs, prel1, gel1);
    {
        dim3 g(F1 / 128, mtiles, TT);
        gemm_bf16_kernel<true><<<g, blk, GEMM_SMEM_BYTES>>>(gel1, Wa1t, ba1, h1b,
            NN, F1, F1, (long)NN*F1, (long)F1*F1, (long)NN*F1, F1);
    }

    // ===================== Layer 2 =====================
    {
        dim3 g(F2 / 128, mtiles, TT);
        gemm_bf16_kernel<true><<<g, blk, GEMM_SMEM_BYTES>>>(h1b, Wk2t, bk2, K2b,
            NN, F2, F1, (long)NN*F1, (long)F1*F2, (long)NN*F2, F2);
        gemm_bf16_kernel<false><<<g, blk, GEMM_SMEM_BYTES>>>(h1b, Wq2t, bq2, Q2,
            NN, F2, F1, (long)NN*F1, (long)F1*F2, (long)NN*F2, F2);
        gemm_bf16_kernel<true><<<g, blk, GEMM_SMEM_BYTES>>>(h1b, Wv2t, bv2, V2b,
            NN, F2, F1, (long)NN*F1, (long)F1*F2, (long)NN*F2, F2);
    }
    {
        dim3 g(1, mtiles, 32);
        rel_gemm_bf16_kernel<<<g, blk, GEMM_SMEM_BYTES>>>(K2b, ar2t, Kr2, D2);
        rel_gemm_bf16_kernel<<<g, blk, GEMM_SMEM_BYTES>>>(V2b, mr2t, Vr2, D2);
    }
    attn_fused_kernel<D2><<<dim3(NN, TT), 128>>>(Q2, Kr2, Vr2, off, srcs, prel2, gel2);
    {
        dim3 g(F2 / 128, mtiles, TT);
        gemm_bf16_kernel<true><<<g, blk, GEMM_SMEM_BYTES>>>(gel2, Wa2t, ba2, h2b,
            NN, F2, F2, (long)NN*F2, (long)F2*F2, (long)NN*F2, F2);
    }

    // ===================== Final linear + softmax =====================
    final_softmax_kernel<<<(TT * NN * 32 + 255) / 256, blk>>>(h2b, Wlin, blin, (float*)d_out);
}

// round 17
// speedup vs baseline: 6.6967x; 1.0394x over previous
#include <cuda_runtime.h>
#include <cuda_bf16.h>
#include <math.h>

#define TT   2
#define NN   10000
#define EE   60000
#define HH   8
#define FIN  2048
#define F1   1024
#define D1   128
#define F2   512
#define D2   64
#define NOUT 8

typedef __nv_bfloat16 bf16;

// ---------------- device scratch (no runtime allocation allowed) ----------------
// bf16 activation chain
__device__ bf16 gb_x  [TT*NN*FIN];
__device__ bf16 gb_K1 [TT*NN*F1];
__device__ bf16 gb_V1 [TT*NN*F1];
__device__ bf16 gb_gel1[TT*NN*F1];
__device__ bf16 gb_h1 [TT*NN*F1];
__device__ bf16 gb_K2 [TT*NN*F2];
__device__ bf16 gb_V2 [TT*NN*F2];
__device__ bf16 gb_gel2[TT*NN*F2];
__device__ bf16 gb_h2 [TT*NN*F2];
// bf16 attention operands
__device__ bf16 gb_Q1 [TT*NN*F1];
__device__ bf16 gb_Kr1[4*NN*F1];
__device__ bf16 gb_Vr1[4*NN*F1];
__device__ bf16 gb_Q2 [TT*NN*F2];
__device__ bf16 gb_Kr2[4*NN*F2];
__device__ bf16 gb_Vr2[4*NN*F2];
// transposed bf16 weights [.., N, K]
__device__ bf16 gb_Wk1t[TT*FIN*F1];
__device__ bf16 gb_Wq1t[TT*FIN*F1];
__device__ bf16 gb_Wv1t[TT*FIN*F1];
__device__ bf16 gb_Wa1t[TT*F1*F1];
__device__ bf16 gb_Wk2t[TT*F1*F2];
__device__ bf16 gb_Wq2t[TT*F1*F2];
__device__ bf16 gb_Wv2t[TT*F1*F2];
__device__ bf16 gb_Wa2t[TT*F2*F2];
__device__ bf16 gb_ar1t[4*HH*D1*D1];
__device__ bf16 gb_mr1t[4*HH*D1*D1];
__device__ bf16 gb_ar2t[4*HH*D2*D2];
__device__ bf16 gb_mr2t[4*HH*D2*D2];
// CSR by destination, per edge type
__device__ int g_cnt[4*NN];
__device__ int g_off[4*(NN+1)];
__device__ int g_srcs[4*EE];

// =================== bf16 tensor-core GEMM ===================
#define GBK 32
#define STAGE_ELEMS 4096                 // 128*32 bf16 per tile
#define GEMM_SMEM_BYTES (4 * 2 * STAGE_ELEMS * 2)

__device__ __forceinline__ void cp16(void* dst_smem, const void* src, bool pred)
{
    unsigned d = (unsigned)__cvta_generic_to_shared(dst_smem);
    int sz = pred ? 16 : 0;   // src-size 0 => zero-fill, no global access
    asm volatile("cp.async.cg.shared.global [%0], [%1], 16, %2;\n"
                 :: "r"(d), "l"(src), "r"(sz));
}

__device__ __forceinline__ void ldm4(unsigned r[4], unsigned addr)
{
    asm volatile("ldmatrix.sync.aligned.m8n8.x4.shared.b16 {%0,%1,%2,%3}, [%4];\n"
                 : "=r"(r[0]), "=r"(r[1]), "=r"(r[2]), "=r"(r[3]) : "r"(addr));
}

__device__ __forceinline__ void mma_bf16(float c[4],
                                         unsigned a0, unsigned a1, unsigned a2, unsigned a3,
                                         unsigned b0, unsigned b1)
{
    asm volatile(
        "mma.sync.aligned.m16n8k16.row.col.f32.bf16.bf16.f32 "
        "{%0,%1,%2,%3}, {%4,%5,%6,%7}, {%8,%9}, {%0,%1,%2,%3};\n"
        : "+f"(c[0]), "+f"(c[1]), "+f"(c[2]), "+f"(c[3])
        : "r"(a0), "r"(a1), "r"(a2), "r"(a3), "r"(b0), "r"(b1));
}

// C[M,N] = A[M,K] @ Bt[N,K]^T (+bias). A,Bt bf16 row-major. K % 32 == 0.
template<bool OBF>
__device__ __forceinline__ void gemm_bf16_core(
    bf16* smem,
    const bf16* __restrict__ A, long lda,
    const bf16* __restrict__ Bt, long ldb,
    const float* __restrict__ bias,
    void* __restrict__ Cp, long ldc,
    int M, int N, int K)
{
    bf16* smA = smem;                         // 4 stages A
    bf16* smB = smem + 4 * STAGE_ELEMS;       // 4 stages B

    const int tid  = threadIdx.x;
    const int lane = tid & 31;
    const int wid  = tid >> 5;
    const int wm   = wid & 1;
    const int wn   = wid >> 1;
    const int grp  = lane >> 2;
    const int tg   = lane & 3;
    const int l15  = lane & 15;
    const int cb   = lane >> 4;               // 0/1: chunk half for ldmatrix
    const int sx   = (l15 >> 1) & 3;          // per-lane swizzle XOR (tile-invariant)

    const int m0 = blockIdx.y * 128;
    const int n0 = blockIdx.x * 128;

    float acc[4][4][4];
#pragma unroll
    for (int mt = 0; mt < 4; mt++)
#pragma unroll
        for (int nt = 0; nt < 4; nt++)
#pragma unroll
            for (int i = 0; i < 4; i++) acc[mt][nt][i] = 0.f;

    const int niter = K / GBK;

    auto issue = [&](int tile) {
        if (tile < niter) {
            const int k0 = tile * GBK;
            bf16* Asb = smA + (tile & 3) * STAGE_ELEMS;
            bf16* Bsb = smB + (tile & 3) * STAGE_ELEMS;
#pragma unroll
            for (int j = 0; j < 2; j++) {     // A: 128 rows x 4 chunks = 512
                int i = tid + j * 256;
                int r = i >> 2, c = i & 3;
                int sw = c ^ ((r >> 1) & 3);
                cp16(Asb + r * 32 + sw * 8, A + (long)(m0 + r) * lda + k0 + c * 8,
                     (m0 + r) < M);
            }
#pragma unroll
            for (int j = 0; j < 2; j++) {     // B: 128 n-rows x 4 chunks
                int i = tid + j * 256;
                int r = i >> 2, c = i & 3;
                int sw = c ^ ((r >> 1) & 3);
                cp16(Bsb + r * 32 + sw * 8, Bt + (long)(n0 + r) * ldb + k0 + c * 8,
                     (n0 + r) < N);
            }
        }
        asm volatile("cp.async.commit_group;\n");
    };

    issue(0); issue(1); issue(2);

    unsigned smA_u = (unsigned)__cvta_generic_to_shared(smA);
    unsigned smB_u = (unsigned)__cvta_generic_to_shared(smB);

    for (int it = 0; it < niter; ++it) {
        issue(it + 3);
        asm volatile("cp.async.wait_group 3;\n");
        __syncthreads();

        unsigned aU = smA_u + (it & 3) * (STAGE_ELEMS * 2);
        unsigned bU = smB_u + (it & 3) * (STAGE_ELEMS * 2);

#pragma unroll
        for (int slice = 0; slice < 2; slice++) {
            int cs = ((slice * 2 + cb) ^ sx);
            unsigned a[4][4], b[2][4];
#pragma unroll
            for (int mt = 0; mt < 4; mt++) {
                int r = wm * 64 + mt * 16 + l15;
                ldm4(a[mt], aU + (r * 32 + cs * 8) * 2);
            }
#pragma unroll
            for (int ntp = 0; ntp < 2; ntp++) {
                int r = wn * 32 + ntp * 16 + l15;
                ldm4(b[ntp], bU + (r * 32 + cs * 8) * 2);
            }
#pragma unroll
            for (int mt = 0; mt < 4; mt++)
#pragma unroll
                for (int nt = 0; nt < 4; nt++)
                    mma_bf16(acc[mt][nt],
                             a[mt][0], a[mt][1], a[mt][2], a[mt][3],
                             b[nt >> 1][nt & 1], b[nt >> 1][2 + (nt & 1)]);
        }
        __syncthreads();
    }

    // ---- epilogue: bias + store ----
#pragma unroll
    for (int mt = 0; mt < 4; mt++) {
        int r0 = m0 + wm * 64 + mt * 16 + grp;
#pragma unroll
        for (int nt = 0; nt < 4; nt++) {
            int col = n0 + wn * 32 + nt * 8 + tg * 2;
            if (col >= N) continue;
            float bx = 0.f, by = 0.f;
            if (bias) { bx = bias[col]; by = bias[col + 1]; }
            float v00 = acc[mt][nt][0] + bx, v01 = acc[mt][nt][1] + by;
            float v10 = acc[mt][nt][2] + bx, v11 = acc[mt][nt][3] + by;
            if (OBF) {
                bf16* C = (bf16*)Cp;
                if (r0 < M)
                    *(__nv_bfloat162*)(C + (long)r0 * ldc + col) =
                        __floats2bfloat162_rn(v00, v01);
                if (r0 + 8 < M)
                    *(__nv_bfloat162*)(C + (long)(r0 + 8) * ldc + col) =
                        __floats2bfloat162_rn(v10, v11);
            } else {
                float* C = (float*)Cp;
                if (r0 < M)
                    *(float2*)(C + (long)r0 * ldc + col) = make_float2(v00, v01);
                if (r0 + 8 < M)
                    *(float2*)(C + (long)(r0 + 8) * ldc + col) = make_float2(v10, v11);
            }
        }
    }
}

template<bool OBF>
__global__ __launch_bounds__(256, 2)
void gemm_bf16_kernel(const bf16* __restrict__ A, const bf16* __restrict__ Bt,
                      const float* __restrict__ bias, void* __restrict__ C,
                      int M, int N, int K,
                      long sA, long sB, long sC, long sBias)
{
    extern __shared__ bf16 smem_b[];
    int bz = blockIdx.z;
    gemm_bf16_core<OBF>(smem_b,
                        A + (long)bz * sA, K,
                        Bt + (long)bz * sB, K,
                        bias + (long)bz * sBias,
                        OBF ? (void*)((bf16*)C + (long)bz * sC)
                            : (void*)((float*)C + (long)bz * sC),
                        N, M, N, K);
}

// out[e,n,h,:] = KQV[st,n,h,:] @ relT[e,h]^T  (bf16 out)
__global__ __launch_bounds__(256, 2)
void rel_gemm_bf16_kernel(const bf16* __restrict__ KQV,
                          const bf16* __restrict__ relT,
                          bf16* __restrict__ outp,
                          int D)
{
    extern __shared__ bf16 smem_b[];
    int z = blockIdx.z;            // 0..31
    int e = z >> 3;
    int h = z & 7;
    int st = e >> 1;
    int HD = HH * D;
    gemm_bf16_core<true>(smem_b,
                         KQV + (long)st * NN * HD + h * D, HD,
                         relT + ((long)e * HH + h) * (long)D * D, D,
                         nullptr,
                         outp + (long)e * NN * HD + h * D, HD,
                         NN, D, D);
}

// =================== conversions ===================
__global__ void cvt_bf16_kernel(const float* __restrict__ in, bf16* __restrict__ out, long n4)
{
    long i = (long)blockIdx.x * blockDim.x + threadIdx.x;
    if (i >= n4) return;
    float4 v = ((const float4*)in)[i];
    ((__nv_bfloat162*)out)[2*i]   = __floats2bfloat162_rn(v.x, v.y);
    ((__nv_bfloat162*)out)[2*i+1] = __floats2bfloat162_rn(v.z, v.w);
}

// in [z][K][N] fp32 -> out [z][N][K] bf16. K,N multiples of 32. block (32,8)
__global__ void transpose_cvt_kernel(const float* __restrict__ in, bf16* __restrict__ out,
                                     int K, int N)
{
    __shared__ float t[32][33];
    long zoff = (long)blockIdx.z * K * N;
    int n0 = blockIdx.x * 32, k0 = blockIdx.y * 32;
    int tx = threadIdx.x, ty = threadIdx.y;
#pragma unroll
    for (int s = 0; s < 4; s++)
        t[ty + 8*s][tx] = in[zoff + (long)(k0 + ty + 8*s) * N + n0 + tx];
    __syncthreads();
#pragma unroll
    for (int s = 0; s < 4; s++)
        out[zoff + (long)(n0 + ty + 8*s) * K + k0 + tx] =
            __float2bfloat16(t[tx][ty + 8*s]);
}

// =================== CSR build (by destination, per edge type) ===================
__global__ void zero_int_kernel(int* __restrict__ p, int n)
{
    int i = blockIdx.x * blockDim.x + threadIdx.x;
    if (i < n) p[i] = 0;
}

__global__ void csr_count_kernel(const int* __restrict__ e0, const int* __restrict__ e1,
                                 const int* __restrict__ e2, const int* __restrict__ e3,
                                 int* __restrict__ cnt)
{
    int i = blockIdx.x * blockDim.x + threadIdx.x;
    if (i >= 4 * EE) return;
    int e = i / EE, idx = i % EE;
    const int* p = (e == 0) ? e0 : (e == 1) ? e1 : (e == 2) ? e2 : e3;
    int dst = p[EE + idx];
    atomicAdd(&cnt[e * NN + dst], 1);
}

__global__ void csr_scan_kernel(int* __restrict__ cnt, int* __restrict__ off)
{
    const int C = (NN + 255) / 256;
    int e = blockIdx.x;
    int t = threadIdx.x;
    int base = t * C;
    int sum = 0;
    for (int j = 0; j < C; j++) {
        int i = base + j;
        if (i < NN) sum += cnt[e * NN + i];
    }
    __shared__ int sh[256];
    sh[t] = sum;
    __syncthreads();
    for (int o = 1; o < 256; o <<= 1) {
        int v = (t >= o) ? sh[t - o] : 0;
        __syncthreads();
        sh[t] += v;
        __syncthreads();
    }
    int run = sh[t] - sum;
    for (int j = 0; j < C; j++) {
        int i = base + j;
        if (i < NN) {
            off[e * (NN + 1) + i] = run;
            run += cnt[e * NN + i];
            cnt[e * NN + i] = 0;
        }
    }
    if (t == 0) off[e * (NN + 1) + NN] = EE;
}

__global__ void csr_scatter_kernel(const int* __restrict__ e0, const int* __restrict__ e1,
                                   const int* __restrict__ e2, const int* __restrict__ e3,
                                   const int* __restrict__ off, int* __restrict__ cur,
                                   int* __restrict__ srcs)
{
    int i = blockIdx.x * blockDim.x + threadIdx.x;
    if (i >= 4 * EE) return;
    int e = i / EE, idx = i % EE;
    const int* p = (e == 0) ? e0 : (e == 1) ? e1 : (e == 2) ? e2 : e3;
    int s = p[idx];
    int d = p[EE + idx];
    int pos = atomicAdd(&cur[e * NN + d], 1);
    srcs[e * EE + off[e * (NN + 1) + d] + pos] = s;
}

// =================== fused attention (bf16 operands, fp32 math) ===================
template<int D>
__global__ __launch_bounds__(128)
void attn_fused_kernel(const bf16* __restrict__ Q,     // [TT,NN,H*D]
                       const bf16* __restrict__ Krel,  // [4,NN,H*D]
                       const bf16* __restrict__ Vrel,  // [4,NN,H*D]
                       const int* __restrict__ off,    // [4,NN+1]
                       const int* __restrict__ srcs,   // [4,EE]
                       const float* __restrict__ prel, // [4,H]
                       bf16* __restrict__ gel)         // [TT,NN,H*D] (GELU applied)
{
    constexpr int HD  = HH * D;
    constexpr int VPT = HD / 128;       // 8 (D=128) or 4 (D=64)
    constexpr int NH2 = VPT / 2;

    const int n   = blockIdx.x;
    const int dt  = blockIdx.y;
    const int tid = threadIdx.x;
    const int c0  = tid * VPT;
    const int h   = c0 / D;

    // load VPT bf16 channels as one vector
    auto loadv = [](const bf16* p, __nv_bfloat162 (&dst)[NH2]) {
        if (VPT == 8)      *(uint4*)dst = *(const uint4*)p;
        else               *(uint2*)dst = *(const uint2*)p;
    };

    float q[VPT];
    {
        __nv_bfloat162 qh[NH2];
        loadv(Q + ((long)dt * NN + n) * HD + c0, qh);
#pragma unroll
        for (int u = 0; u < NH2; u++) {
            float2 f = __bfloat1622float2(qh[u]);
            q[2*u] = f.x; q[2*u+1] = f.y;
        }
    }
    const float inv = rsqrtf((float)D);

    float outacc[VPT];
#pragma unroll
    for (int j = 0; j < VPT; j++) outacc[j] = 0.f;

#pragma unroll
    for (int pass = 0; pass < 2; pass++) {
        const int e   = dt + 2 * pass;
        const int beg = off[e * (NN + 1) + n];
        const int end = off[e * (NN + 1) + n + 1];
        const float pr = prel[e * HH + h] * inv;
        const bf16* Kb = Krel + (long)e * NN * HD;
        const bf16* Vb = Vrel + (long)e * NN * HD;
        const int* sp = srcs + (long)e * EE;

        float m = -INFINITY, s = 0.f;
        float acc[VPT];
#pragma unroll
        for (int j = 0; j < VPT; j++) acc[j] = 0.f;

        for (int idx = beg; idx < end; idx++) {
            int src = sp[idx];
            __nv_bfloat162 kh[NH2], vh[NH2];
            loadv(Kb + (long)src * HD + c0, kh);
            loadv(Vb + (long)src * HD + c0, vh);
            float kv[VPT], vv[VPT];
#pragma unroll
            for (int u = 0; u < NH2; u++) {
                float2 a = __bfloat1622float2(kh[u]);
                kv[2*u] = a.x; kv[2*u+1] = a.y;
                float2 b = __bfloat1622float2(vh[u]);
                vv[2*u] = b.x; vv[2*u+1] = b.y;
            }
            float dotp = 0.f;
#pragma unroll
            for (int j = 0; j < VPT; j++) dotp += q[j] * kv[j];
#pragma unroll
            for (int o = 8; o; o >>= 1)
                dotp += __shfl_xor_sync(0xffffffffu, dotp, o, 16);
            float logit = dotp * pr;
            float mnew  = fmaxf(m, logit);
            float co    = __expf(m - mnew);
            float p     = __expf(logit - mnew);
            s = s * co + p;
#pragma unroll
            for (int j = 0; j < VPT; j++) acc[j] = acc[j] * co + p * vv[j];
            m = mnew;
        }
        if (s > 0.f) {
            float is = 1.f / s;
#pragma unroll
            for (int j = 0; j < VPT; j++) outacc[j] += acc[j] * is;
        }
    }

    __nv_bfloat162* o2 = (__nv_bfloat162*)(gel + ((long)dt * NN + n) * HD + c0);
#pragma unroll
    for (int j = 0; j < VPT; j += 2) {
        float x0 = outacc[j], x1 = outacc[j+1];
        float g0 = 0.5f * x0 * (1.0f + erff(x0 * 0.7071067811865476f));
        float g1 = 0.5f * x1 * (1.0f + erff(x1 * 0.7071067811865476f));
        o2[j >> 1] = __floats2bfloat162_rn(g0, g1);
    }
}

// ---------------- final: logits = h @ Wlin + blin; row softmax ----------------
__global__ void final_softmax_kernel(const bf16* __restrict__ h,    // [TT*NN, F2]
                                     const float* __restrict__ Wlin,// [F2, NOUT]
                                     const float* __restrict__ blin,// [NOUT]
                                     float* __restrict__ out)       // [TT*NN, NOUT]
{
    int row = (blockIdx.x * blockDim.x + threadIdx.x) >> 5;
    if (row >= TT * NN) return;
    int lane = threadIdx.x & 31;
    const bf16* hr = h + (long)row * F2;
    float acc[NOUT];
#pragma unroll
    for (int o = 0; o < NOUT; o++) acc[o] = 0.f;
    for (int f = lane; f < F2; f += 32) {
        float hv = __bfloat162float(hr[f]);
#pragma unroll
        for (int o = 0; o < NOUT; o++) acc[o] += hv * Wlin[f * NOUT + o];
    }
#pragma unroll
    for (int o = 0; o < NOUT; o++)
#pragma unroll
        for (int s = 16; s; s >>= 1) acc[o] += __shfl_xor_sync(0xffffffffu, acc[o], s);
    if (lane == 0) {
        float vals[NOUT];
        float m = -INFINITY;
#pragma unroll
        for (int o = 0; o < NOUT; o++) { vals[o] = acc[o] + blin[o]; m = fmaxf(m, vals[o]); }
        float s = 0.f;
#pragma unroll
        for (int o = 0; o < NOUT; o++) { vals[o] = __expf(vals[o] - m); s += vals[o]; }
        float invs = 1.0f / s;
#pragma unroll
        for (int o = 0; o < NOUT; o++) out[(long)row * NOUT + o] = vals[o] * invs;
    }
}

// ---------------- host orchestration ----------------
static void* symv(const void* s)
{
    void* p = nullptr;
    cudaGetSymbolAddress(&p, (const void*)s);
    return p;
}

extern "C" void kernel_launch(void* const* d_in, const int* in_sizes, int n_in,
                              void* d_out, int out_size)
{
    const float* x  = (const float*)d_in[0];
    const int* e0 = (const int*)d_in[1];
    const int* e1 = (const int*)d_in[2];
    const int* e2 = (const int*)d_in[3];
    const int* e3 = (const int*)d_in[4];
    const float* Wk1 = (const float*)d_in[5];  const float* bk1 = (const float*)d_in[6];
    const float* Wq1 = (const float*)d_in[7];  const float* bq1 = (const float*)d_in[8];
    const float* Wv1 = (const float*)d_in[9];  const float* bv1 = (const float*)d_in[10];
    const float* Wa1 = (const float*)d_in[11]; const float* ba1 = (const float*)d_in[12];
    const float* arel1 = (const float*)d_in[13];
    const float* mrel1 = (const float*)d_in[14];
    const float* prel1 = (const float*)d_in[15];
    const float* Wk2 = (const float*)d_in[16]; const float* bk2 = (const float*)d_in[17];
    const float* Wq2 = (const float*)d_in[18]; const float* bq2 = (const float*)d_in[19];
    const float* Wv2 = (const float*)d_in[20]; const float* bv2 = (const float*)d_in[21];
    const float* Wa2 = (const float*)d_in[22]; const float* ba2 = (const float*)d_in[23];
    const float* arel2 = (const float*)d_in[24];
    const float* mrel2 = (const float*)d_in[25];
    const float* prel2 = (const float*)d_in[26];
    const float* Wlin  = (const float*)d_in[27];
    const float* blin  = (const float*)d_in[28];

    bf16* xb   = (bf16*)symv(gb_x);
    bf16* K1b  = (bf16*)symv(gb_K1);  bf16* V1b = (bf16*)symv(gb_V1);
    bf16* gel1 = (bf16*)symv(gb_gel1); bf16* h1b = (bf16*)symv(gb_h1);
    bf16* K2b  = (bf16*)symv(gb_K2);  bf16* V2b = (bf16*)symv(gb_V2);
    bf16* gel2 = (bf16*)symv(gb_gel2); bf16* h2b = (bf16*)symv(gb_h2);
    bf16* Q1b  = (bf16*)symv(gb_Q1);
    bf16* Kr1  = (bf16*)symv(gb_Kr1); bf16* Vr1 = (bf16*)symv(gb_Vr1);
    bf16* Q2b  = (bf16*)symv(gb_Q2);
    bf16* Kr2  = (bf16*)symv(gb_Kr2); bf16* Vr2 = (bf16*)symv(gb_Vr2);
    bf16* Wk1t = (bf16*)symv(gb_Wk1t); bf16* Wq1t = (bf16*)symv(gb_Wq1t);
    bf16* Wv1t = (bf16*)symv(gb_Wv1t); bf16* Wa1t = (bf16*)symv(gb_Wa1t);
    bf16* Wk2t = (bf16*)symv(gb_Wk2t); bf16* Wq2t = (bf16*)symv(gb_Wq2t);
    bf16* Wv2t = (bf16*)symv(gb_Wv2t); bf16* Wa2t = (bf16*)symv(gb_Wa2t);
    bf16* ar1t = (bf16*)symv(gb_ar1t); bf16* mr1t = (bf16*)symv(gb_mr1t);
    bf16* ar2t = (bf16*)symv(gb_ar2t); bf16* mr2t = (bf16*)symv(gb_mr2t);
    int* cnt  = (int*)symv(g_cnt);
    int* off  = (int*)symv(g_off);
    int* srcs = (int*)symv(g_srcs);

    cudaFuncSetAttribute(gemm_bf16_kernel<true>,
                         cudaFuncAttributeMaxDynamicSharedMemorySize, GEMM_SMEM_BYTES);
    cudaFuncSetAttribute(gemm_bf16_kernel<false>,
                         cudaFuncAttributeMaxDynamicSharedMemorySize, GEMM_SMEM_BYTES);
    cudaFuncSetAttribute(rel_gemm_bf16_kernel,
                         cudaFuncAttributeMaxDynamicSharedMemorySize, GEMM_SMEM_BYTES);

    dim3 blk(256);
    dim3 tb(32, 8);
    const int mtiles = (NN + 127) / 128;   // 79

    // ---- conversions (weights + input) ----
    {
        long n4 = (long)TT * NN * FIN / 4;
        cvt_bf16_kernel<<<(unsigned)((n4 + 255) / 256), 256>>>(x, xb, n4);
        transpose_cvt_kernel<<<dim3(F1/32, FIN/32, TT), tb>>>(Wk1, Wk1t, FIN, F1);
        transpose_cvt_kernel<<<dim3(F1/32, FIN/32, TT), tb>>>(Wq1, Wq1t, FIN, F1);
        transpose_cvt_kernel<<<dim3(F1/32, FIN/32, TT), tb>>>(Wv1, Wv1t, FIN, F1);
        transpose_cvt_kernel<<<dim3(F1/32, F1/32, TT),  tb>>>(Wa1, Wa1t, F1, F1);
        transpose_cvt_kernel<<<dim3(F2/32, F1/32, TT),  tb>>>(Wk2, Wk2t, F1, F2);
        transpose_cvt_kernel<<<dim3(F2/32, F1/32, TT),  tb>>>(Wq2, Wq2t, F1, F2);
        transpose_cvt_kernel<<<dim3(F2/32, F1/32, TT),  tb>>>(Wv2, Wv2t, F1, F2);
        transpose_cvt_kernel<<<dim3(F2/32, F2/32, TT),  tb>>>(Wa2, Wa2t, F2, F2);
        transpose_cvt_kernel<<<dim3(D1/32, D1/32, 32),  tb>>>(arel1, ar1t, D1, D1);
        transpose_cvt_kernel<<<dim3(D1/32, D1/32, 32),  tb>>>(mrel1, mr1t, D1, D1);
        transpose_cvt_kernel<<<dim3(D2/32, D2/32, 32),  tb>>>(arel2, ar2t, D2, D2);
        transpose_cvt_kernel<<<dim3(D2/32, D2/32, 32),  tb>>>(mrel2, mr2t, D2, D2);
    }

    // ---- CSR build ----
    zero_int_kernel<<<(4 * NN + 255) / 256, 256>>>(cnt, 4 * NN);
    csr_count_kernel<<<(4 * EE + 255) / 256, 256>>>(e0, e1, e2, e3, cnt);
    csr_scan_kernel<<<4, 256>>>(cnt, off);
    csr_scatter_kernel<<<(4 * EE + 255) / 256, 256>>>(e0, e1, e2, e3, off, cnt, srcs);

    // ===================== Layer 1 =====================
    {
        dim3 g(F1 / 128, mtiles, TT);
        gemm_bf16_kernel<true><<<g, blk, GEMM_SMEM_BYTES>>>(xb, Wk1t, bk1, K1b,
            NN, F1, FIN, (long)NN*FIN, (long)FIN*F1, (long)NN*F1, F1);
        gemm_bf16_kernel<true><<<g, blk, GEMM_SMEM_BYTES>>>(xb, Wq1t, bq1, Q1b,
            NN, F1, FIN, (long)NN*FIN, (long)FIN*F1, (long)NN*F1, F1);
        gemm_bf16_kernel<true><<<g, blk, GEMM_SMEM_BYTES>>>(xb, Wv1t, bv1, V1b,
            NN, F1, FIN, (long)NN*FIN, (long)FIN*F1, (long)NN*F1, F1);
    }
    {
        dim3 g(1, mtiles, 32);
        rel_gemm_bf16_kernel<<<g, blk, GEMM_SMEM_BYTES>>>(K1b, ar1t, Kr1, D1);
        rel_gemm_bf16_kernel<<<g, blk, GEMM_SMEM_BYTES>>>(V1b, mr1t, Vr1, D1);
    }
    attn_fused_kernel<D1><<<dim3(NN, TT), 128>>>(Q1b, Kr1, Vr1, off, srcs, prel1, gel1);
    {
        dim3 g(F1 / 128, mtiles, TT);
        gemm_bf16_kernel<true><<<g, blk, GEMM_SMEM_BYTES>>>(gel1, Wa1t, ba1, h1b,
            NN, F1, F1, (long)NN*F1, (long)F1*F1, (long)NN*F1, F1);
    }

    // ===================== Layer 2 =====================
    {
        dim3 g(F2 / 128, mtiles, TT);
        gemm_bf16_kernel<true><<<g, blk, GEMM_SMEM_BYTES>>>(h1b, Wk2t, bk2, K2b,
            NN, F2, F1, (long)NN*F1, (long)F1*F2, (long)NN*F2, F2);
        gemm_bf16_kernel<true><<<g, blk, GEMM_SMEM_BYTES>>>(h1b, Wq2t, bq2, Q2b,
            NN, F2, F1, (long)NN*F1, (long)F1*F2, (long)NN*F2, F2);
        gemm_bf16_kernel<true><<<g, blk, GEMM_SMEM_BYTES>>>(h1b, Wv2t, bv2, V2b,
            NN, F2, F1, (long)NN*F1, (long)F1*F2, (long)NN*F2, F2);
    }
    {
        dim3 g(1, mtiles, 32);
        rel_gemm_bf16_kernel<<<g, blk, GEMM_SMEM_BYTES>>>(K2b, ar2t, Kr2, D2);
        rel_gemm_bf16_kernel<<<g, blk, GEMM_SMEM_BYTES>>>(V2b, mr2t, Vr2, D2);
    }
    attn_fused_kernel<D2><<<dim3(NN, TT), 128>>>(Q2b, Kr2, Vr2, off, srcs, prel2, gel2);
    {
        dim3 g(F2 / 128, mtiles, TT);
        gemm_bf16_kernel<true><<<g, blk, GEMM_SMEM_BYTES>>>(gel2, Wa2t, ba2, h2b,
            NN, F2, F2, (long)NN*F2, (long)F2*F2, (long)NN*F2, F2);
    }

    // ===================== Final linear + softmax =====================
    final_softmax_kernel<<<(TT * NN * 32 + 255) / 256, blk>>>(h2b, Wlin, blin, (float*)d_out);
}